// round 10
// baseline (speedup 1.0000x reference)
#include <cuda_runtime.h>
#include <math.h>
#include <stdint.h>

#define NL   4
#define NB   4
#define SEQ  2048
#define DM   256
#define NH   8
#define DH   32
#define DF   512
#define MR   (NB*SEQ)

#define NEGF (-3.402823466e38f)
#define L2E  1.44269504088896340736f

typedef unsigned long long u64;

// ================= bf16 helpers =================
__device__ __forceinline__ uint32_t pack_bf16x2(float lo, float hi) {
    uint32_t r; asm("cvt.rn.bf16x2.f32 %0, %1, %2;" : "=r"(r) : "f"(hi), "f"(lo)); return r;
}
__device__ __forceinline__ float bf_low(uint32_t p)  { return __uint_as_float(p << 16); }
__device__ __forceinline__ float bf_high(uint32_t p) { return __uint_as_float(p & 0xffff0000u); }
__device__ __forceinline__ float ex2f(float x) {
    float r; asm("ex2.approx.f32 %0, %1;" : "=f"(r) : "f"(x)); return r;
}

__device__ __forceinline__ void mma_bf16(float* c, const uint32_t* a, const uint32_t* b) {
    asm volatile(
        "mma.sync.aligned.m16n8k16.row.col.f32.bf16.bf16.f32 "
        "{%0,%1,%2,%3},{%4,%5,%6,%7},{%8,%9},{%0,%1,%2,%3};"
        : "+f"(c[0]), "+f"(c[1]), "+f"(c[2]), "+f"(c[3])
        : "r"(a[0]), "r"(a[1]), "r"(a[2]), "r"(a[3]), "r"(b[0]), "r"(b[1]));
}

// ================= scratch =================
__device__ float g_qkv [3*(size_t)MR*DM];
__device__ float g_obuf[(size_t)MR*DM];
__device__ float g_xc  [(size_t)MR*DM];
__device__ float g_ff  [(size_t)MR*DF];

// packed K: [bh][dim-pair 16][key 2048] hi/lo;  packed V: [bh][dim 32][key-pair 1024] hi/lo
__device__ uint32_t g_kph[NB*NH*16*SEQ];
__device__ uint32_t g_kpl[NB*NH*16*SEQ];
__device__ uint32_t g_vph[NB*NH*32*(SEQ/2)];
__device__ uint32_t g_vpl[NB*NH*32*(SEQ/2)];
__device__ unsigned g_kmax2[NB*NH];        // max ||k||^2 per (b,h), float bits

// packed bf16 hi/lo weights
__device__ uint32_t g_pwqkv_h[NL*3*DM*(DM/2)];
__device__ uint32_t g_pwqkv_l[NL*3*DM*(DM/2)];
__device__ uint32_t g_pwo_h  [NL*DM*(DM/2)];
__device__ uint32_t g_pwo_l  [NL*DM*(DM/2)];
__device__ uint32_t g_pw1_h  [NL*DF*(DM/2)];
__device__ uint32_t g_pw1_l  [NL*DF*(DM/2)];
__device__ uint32_t g_pw2_h  [NL*DM*(DF/2)];
__device__ uint32_t g_pw2_l  [NL*DM*(DF/2)];

// ================= weight packing =================
__global__ void pack_qkv(const float* __restrict__ Wq,
                         const float* __restrict__ Wk,
                         const float* __restrict__ Wv) {
    int i = blockIdx.x * blockDim.x + threadIdx.x;
    const int PER_M = DM * (DM/2);
    const int TOT = NL * 3 * PER_M;
    if (i >= TOT) return;
    int l  = i / (3*PER_M);
    int r  = i % (3*PER_M);
    int m  = r / PER_M;
    int r2 = r % PER_M;
    int n  = r2 >> 7;
    int kp = r2 & 127;
    int h = n >> 5, e = n & 31;
    const float* W = (m == 0) ? Wq : (m == 1) ? Wk : Wv;
    size_t s0 = (((size_t)l*NH + h)*DM + 2*kp)*DH + e;
    float v0 = W[s0], v1 = W[s0 + DH];
    uint32_t hp = pack_bf16x2(v0, v1);
    g_pwqkv_h[i] = hp;
    g_pwqkv_l[i] = pack_bf16x2(v0 - bf_low(hp), v1 - bf_high(hp));
}

__global__ void pack_w(const float* __restrict__ W, uint32_t* __restrict__ dh,
                       uint32_t* __restrict__ dl, int K, int N) {
    int i = blockIdx.x * blockDim.x + threadIdx.x;
    int per = N * (K >> 1);
    if (i >= NL * per) return;
    int l = i / per, r = i % per;
    int n = r / (K >> 1), kp = r % (K >> 1);
    size_t s = (size_t)l*K*N + (size_t)(2*kp)*N + n;
    float v0 = W[s], v1 = W[s + N];
    uint32_t hp = pack_bf16x2(v0, v1);
    dh[i] = hp;
    dl[i] = pack_bf16x2(v0 - bf_low(hp), v1 - bf_high(hp));
}

// ================= K/V transpose + split-bf16 pack (+ K norm max) ==========
__global__ void pack_kv(const float* __restrict__ k, const float* __restrict__ v) {
    __shared__ float tl[32][33];
    int bh = blockIdx.y;
    int b = bh >> 3, h = bh & 7;
    int l0 = blockIdx.x * 32;
    const float* src = (blockIdx.z == 0) ? k : v;
    #pragma unroll
    for (int kk = 0; kk < 4; kk++) {
        int l = l0 + threadIdx.y + kk*8;
        tl[threadIdx.y + kk*8][threadIdx.x] = src[((size_t)b*SEQ + l)*DM + h*32 + threadIdx.x];
    }
    __syncthreads();
    if (blockIdx.z == 0) {
        #pragma unroll
        for (int kk = 0; kk < 2; kk++) {
            int dp = threadIdx.y + kk*8;
            float v0 = tl[threadIdx.x][2*dp], v1 = tl[threadIdx.x][2*dp+1];
            uint32_t hp = pack_bf16x2(v0, v1);
            size_t o = ((size_t)bh*16 + dp)*SEQ + l0 + threadIdx.x;
            g_kph[o] = hp;
            g_kpl[o] = pack_bf16x2(v0 - bf_low(hp), v1 - bf_high(hp));
        }
        if (threadIdx.y == 0) {
            float n2 = 0.f;
            #pragma unroll
            for (int e = 0; e < 32; e++) n2 = fmaf(tl[threadIdx.x][e], tl[threadIdx.x][e], n2);
            #pragma unroll
            for (int d = 16; d > 0; d >>= 1)
                n2 = fmaxf(n2, __shfl_xor_sync(0xffffffffu, n2, d));
            if (threadIdx.x == 0)
                atomicMax(&g_kmax2[bh], __float_as_uint(n2));
        }
    } else {
        #pragma unroll
        for (int kk = 0; kk < 2; kk++) {
            int idx = threadIdx.y*32 + threadIdx.x + kk*256;
            int e = idx >> 4, lp = idx & 15;
            float v0 = tl[2*lp][e], v1 = tl[2*lp+1][e];
            uint32_t hp = pack_bf16x2(v0, v1);
            size_t o = ((size_t)bh*32 + e)*(SEQ/2) + (l0 >> 1) + lp;
            g_vph[o] = hp;
            g_vpl[o] = pack_bf16x2(v0 - bf_low(hp), v1 - bf_high(hp));
        }
    }
}

// ================= HMMA GEMM (bf16 3-term, double-buffered) =================
#define GBM 128
#define GBN 64
#define GBK 32
#define AKP (GBK/2)
#define APAD 20

__device__ __forceinline__ float gelu_exact(float x) {
    return 0.5f * x * (1.0f + erff(x * 0.70710678118654752440f));
}

__device__ __forceinline__ void epi2(float* C, size_t off, float c0, float c1,
                                     float2 bb, const float* res, int mode) {
    float2 o;
    if (mode == 1) {
        float2 r = *(const float2*)(res + off);
        o.x = (c0 + r.x)*0.5f; o.y = (c1 + r.y)*0.5f;
    } else if (mode == 2) {
        o.x = gelu_exact(c0 + bb.x); o.y = gelu_exact(c1 + bb.y);
    } else if (mode == 3) {
        float2 r = *(const float2*)(res + off);
        o.x = (c0 + bb.x + r.x)*0.5f; o.y = (c1 + bb.y + r.y)*0.5f;
    } else {
        o.x = c0; o.y = c1;
    }
    *(float2*)(C + off) = o;
}

extern __shared__ uint32_t dsm[];

__global__ __launch_bounds__(256, 2)
void gemm_mma(const float* __restrict__ A, const uint32_t* __restrict__ Bh,
              const uint32_t* __restrict__ Bl, const float* __restrict__ bias,
              const float* __restrict__ res, float* __restrict__ C,
              int M, int N, int K, int mode) {
    uint32_t* Ash = dsm;
    uint32_t* Bsh = dsm + 2*2*GBM*APAD;

    if (mode == 0) {
        int z = blockIdx.z;
        Bh += (size_t)z * DM * (DM/2);
        Bl += (size_t)z * DM * (DM/2);
        C  += (size_t)z * (size_t)M * N;
        // fold kmax reset into QKV GEMM (runs before pack_kv in-stream)
        if (blockIdx.x == 0 && blockIdx.y == 0 && z == 0 && threadIdx.x < NB*NH)
            g_kmax2[threadIdx.x] = 0u;
    }
    int bm = blockIdx.y * GBM;
    int bn = blockIdx.x * GBN;
    int tid = threadIdx.x;
    int warp = tid >> 5, lane = tid & 31;
    int g = lane >> 2, j = lane & 3;
    int wm = (warp & 3) * 32;
    int wn = (warp >> 2) * 32;
    int ldkp = K >> 1;

    int arow = tid >> 3;
    int akp0 = (tid & 7) * 2;
    int bn0  = tid >> 2;
    int bkp0 = (tid & 3) * 4;

    const float* ap[4];
    #pragma unroll
    for (int s = 0; s < 4; s++)
        ap[s] = A + (size_t)(bm + arow + 32*s)*K + (tid & 7)*4;
    const uint32_t* bph = Bh + (size_t)(bn + bn0)*ldkp + bkp0;
    const uint32_t* bpl = Bl + (size_t)(bn + bn0)*ldkp + bkp0;

    float acc[2][4][4];
    #pragma unroll
    for (int mt = 0; mt < 2; mt++)
        #pragma unroll
        for (int n = 0; n < 4; n++)
            #pragma unroll
            for (int r = 0; r < 4; r++) acc[mt][n][r] = 0.f;

    int nt = K / GBK;
    float4 af[4]; uint4 bfh, bfl;
    #pragma unroll
    for (int s = 0; s < 4; s++) af[s] = *(const float4*)ap[s];
    bfh = *(const uint4*)bph;
    bfl = *(const uint4*)bpl;

    {
        #pragma unroll
        for (int s = 0; s < 4; s++) {
            float4 v = af[s];
            uint32_t h0 = pack_bf16x2(v.x, v.y);
            uint32_t h1 = pack_bf16x2(v.z, v.w);
            uint32_t l0 = pack_bf16x2(v.x - bf_low(h0), v.y - bf_high(h0));
            uint32_t l1 = pack_bf16x2(v.z - bf_low(h1), v.w - bf_high(h1));
            int row = arow + 32*s;
            uint32_t* ph = Ash + row*APAD + akp0;
            uint32_t* pl = Ash + GBM*APAD + row*APAD + akp0;
            ph[0] = h0; ph[1] = h1; pl[0] = l0; pl[1] = l1;
        }
        uint32_t* ph = Bsh + bn0*APAD + bkp0;
        uint32_t* pl = Bsh + GBN*APAD + bn0*APAD + bkp0;
        ph[0]=bfh.x; ph[1]=bfh.y; ph[2]=bfh.z; ph[3]=bfh.w;
        pl[0]=bfl.x; pl[1]=bfl.y; pl[2]=bfl.z; pl[3]=bfl.w;
    }
    __syncthreads();

    for (int t = 0; t < nt; t++) {
        int buf = t & 1;
        if (t + 1 < nt) {
            int k0 = (t+1)*GBK;
            #pragma unroll
            for (int s = 0; s < 4; s++) af[s] = *(const float4*)(ap[s] + k0);
            bfh = *(const uint4*)(bph + (t+1)*AKP);
            bfl = *(const uint4*)(bpl + (t+1)*AKP);
        }

        const uint32_t* Ab = Ash + buf*2*GBM*APAD;
        const uint32_t* Bb = Bsh + buf*2*GBN*APAD;
        #pragma unroll
        for (int kc = 0; kc < 2; kc++) {
            uint32_t ah[2][4], al[2][4];
            #pragma unroll
            for (int mt = 0; mt < 2; mt++) {
                int r0 = wm + mt*16 + g;
                const uint32_t* pa  = Ab;
                const uint32_t* pal = Ab + GBM*APAD;
                ah[mt][0] = pa [(r0)  *APAD + kc*8 + j];
                ah[mt][1] = pa [(r0+8)*APAD + kc*8 + j];
                ah[mt][2] = pa [(r0)  *APAD + kc*8 + j + 4];
                ah[mt][3] = pa [(r0+8)*APAD + kc*8 + j + 4];
                al[mt][0] = pal[(r0)  *APAD + kc*8 + j];
                al[mt][1] = pal[(r0+8)*APAD + kc*8 + j];
                al[mt][2] = pal[(r0)  *APAD + kc*8 + j + 4];
                al[mt][3] = pal[(r0+8)*APAD + kc*8 + j + 4];
            }
            #pragma unroll
            for (int n = 0; n < 4; n++) {
                int c0 = wn + n*8 + g;
                uint32_t bh2[2], bl2[2];
                bh2[0] = Bb[c0*APAD + kc*8 + j];
                bh2[1] = Bb[c0*APAD + kc*8 + j + 4];
                bl2[0] = Bb[GBN*APAD + c0*APAD + kc*8 + j];
                bl2[1] = Bb[GBN*APAD + c0*APAD + kc*8 + j + 4];
                #pragma unroll
                for (int mt = 0; mt < 2; mt++) {
                    mma_bf16(acc[mt][n], ah[mt], bh2);
                    mma_bf16(acc[mt][n], al[mt], bh2);
                    mma_bf16(acc[mt][n], ah[mt], bl2);
                }
            }
        }

        if (t + 1 < nt) {
            int nb = buf ^ 1;
            uint32_t* An = Ash + nb*2*GBM*APAD;
            uint32_t* Bn = Bsh + nb*2*GBN*APAD;
            #pragma unroll
            for (int s = 0; s < 4; s++) {
                float4 v = af[s];
                uint32_t h0 = pack_bf16x2(v.x, v.y);
                uint32_t h1 = pack_bf16x2(v.z, v.w);
                uint32_t l0 = pack_bf16x2(v.x - bf_low(h0), v.y - bf_high(h0));
                uint32_t l1 = pack_bf16x2(v.z - bf_low(h1), v.w - bf_high(h1));
                int row = arow + 32*s;
                uint32_t* ph = An + row*APAD + akp0;
                uint32_t* pl = An + GBM*APAD + row*APAD + akp0;
                ph[0] = h0; ph[1] = h1; pl[0] = l0; pl[1] = l1;
            }
            uint32_t* ph = Bn + bn0*APAD + bkp0;
            uint32_t* pl = Bn + GBN*APAD + bn0*APAD + bkp0;
            ph[0]=bfh.x; ph[1]=bfh.y; ph[2]=bfh.z; ph[3]=bfh.w;
            pl[0]=bfl.x; pl[1]=bfl.y; pl[2]=bfl.z; pl[3]=bfl.w;
        }
        __syncthreads();
    }

    float2 bb[4];
    #pragma unroll
    for (int n = 0; n < 4; n++) {
        if (mode == 2 || mode == 3)
            bb[n] = *(const float2*)(bias + bn + wn + n*8 + 2*j);
        else
            bb[n] = make_float2(0.f, 0.f);
    }
    #pragma unroll
    for (int mt = 0; mt < 2; mt++) {
        int r0 = bm + wm + mt*16 + g;
        #pragma unroll
        for (int n = 0; n < 4; n++) {
            int col = bn + wn + n*8 + 2*j;
            size_t o0 = (size_t)r0*N + col;
            size_t o1 = (size_t)(r0 + 8)*N + col;
            epi2(C, o0, acc[mt][n][0], acc[mt][n][1], bb[n], res, mode);
            epi2(C, o1, acc[mt][n][2], acc[mt][n][3], bb[n], res, mode);
        }
    }
}

// ================= warp-MMA flash attention (static bound, exp2, occ4) ======
#define KT  32
#define NIT (SEQ/KT)

__global__ __launch_bounds__(128, 4)
void attn_mma(const float* __restrict__ gq, const float* __restrict__ gmask,
              float* __restrict__ go) {
    __shared__ __align__(16) uint32_t Ksh[2][2][16][40];
    __shared__ __align__(16) uint32_t Vsh[2][2][32][20];
    __shared__ float sMask[2][KT];   // stores (1-mk)*NEGF

    int tid  = threadIdx.x;
    int warp = tid >> 5;
    int lane = tid & 31;
    int g    = lane >> 2;
    int j    = lane & 3;
    int bh   = blockIdx.y;
    int b    = bh >> 3, h = bh & 7;
    int q0   = blockIdx.x * 128 + warp * 32;

    // Q fragments, pre-scaled by log2(e) so softmax runs in ex2 domain
    uint32_t qh[2][2][4], ql[2][2][4];
    float qn2[2][2] = {};
    #pragma unroll
    for (int mt = 0; mt < 2; mt++) {
        #pragma unroll
        for (int rr = 0; rr < 2; rr++) {
            int row = q0 + mt*16 + g + rr*8;
            const float* qp = gq + ((size_t)b*SEQ + row)*DM + h*DH;
            #pragma unroll
            for (int u = 0; u < 4; u++) {
                float2 v = *(const float2*)(qp + u*8 + 2*j);
                v.x *= L2E; v.y *= L2E;
                qn2[mt][rr] = fmaf(v.x, v.x, fmaf(v.y, v.y, qn2[mt][rr]));
                uint32_t hp = pack_bf16x2(v.x, v.y);
                uint32_t lp = pack_bf16x2(v.x - bf_low(hp), v.y - bf_high(hp));
                qh[mt][u>>1][rr + 2*(u&1)] = hp;
                ql[mt][u>>1][rr + 2*(u&1)] = lp;
            }
        }
    }
    #pragma unroll
    for (int mt = 0; mt < 2; mt++)
        #pragma unroll
        for (int rr = 0; rr < 2; rr++) {
            qn2[mt][rr] += __shfl_xor_sync(0xffffffffu, qn2[mt][rr], 1);
            qn2[mt][rr] += __shfl_xor_sync(0xffffffffu, qn2[mt][rr], 2);
        }

    // |q*L2E| * |k| bounds  q.k*L2E  (k not scaled)
    float kmaxn = sqrtf(__uint_as_float(g_kmax2[bh]));
    float fm[2][2], cb[2][2];
    #pragma unroll
    for (int mt = 0; mt < 2; mt++) {
        fm[mt][0] = gmask[b*SEQ + q0 + mt*16 + g];
        fm[mt][1] = gmask[b*SEQ + q0 + mt*16 + g + 8];
        #pragma unroll
        for (int rr = 0; rr < 2; rr++)
            cb[mt][rr] = (fm[mt][rr] == 0.f) ? 0.f
                       : -(sqrtf(qn2[mt][rr]) * kmaxn - 43.2808512266689f);
    }

    float lrow[2][2], ofr[2][4][4];
    #pragma unroll
    for (int mt = 0; mt < 2; mt++) {
        lrow[mt][0] = 0.f; lrow[mt][1] = 0.f;
        #pragma unroll
        for (int nd = 0; nd < 4; nd++)
            #pragma unroll
            for (int r = 0; r < 4; r++) ofr[mt][nd][r] = 0.f;
    }

    int kdp = tid >> 3;
    int kkg = (tid & 7) * 4;
    int vdm = tid >> 2;
    int vpg = (tid & 3) * 4;
    const uint32_t* kbh = g_kph + ((size_t)bh*16 + kdp)*SEQ + kkg;
    const uint32_t* kbl = g_kpl + ((size_t)bh*16 + kdp)*SEQ + kkg;
    const uint32_t* vbh = g_vph + ((size_t)bh*32 + vdm)*(SEQ/2) + vpg;
    const uint32_t* vbl = g_vpl + ((size_t)bh*32 + vdm)*(SEQ/2) + vpg;
    const float* mbase = gmask + b*SEQ + tid;

    uint4 rkh, rkl, rvh, rvl; float ml = 0.f;
    rkh = *(const uint4*)(kbh);
    rkl = *(const uint4*)(kbl);
    rvh = *(const uint4*)(vbh);
    rvl = *(const uint4*)(vbl);
    if (tid < KT) ml = *mbase;

    *(uint4*)&Ksh[0][0][kdp][kkg] = rkh;
    *(uint4*)&Ksh[0][1][kdp][kkg] = rkl;
    *(uint4*)&Vsh[0][0][vdm][vpg] = rvh;
    *(uint4*)&Vsh[0][1][vdm][vpg] = rvl;
    if (tid < KT) sMask[0][tid] = (1.0f - ml) * NEGF;
    __syncthreads();

    for (int it = 0; it < NIT; it++) {
        int bufc = it & 1;
        if (it + 1 < NIT) {
            rkh = *(const uint4*)(kbh + (it+1)*KT);
            rkl = *(const uint4*)(kbl + (it+1)*KT);
            rvh = *(const uint4*)(vbh + (it+1)*(KT/2));
            rvl = *(const uint4*)(vbl + (it+1)*(KT/2));
            if (tid < KT) ml = mbase[(it+1)*KT];
        }

        float sfr[2][4][4];
        #pragma unroll
        for (int mt = 0; mt < 2; mt++)
            #pragma unroll
            for (int n = 0; n < 4; n++)
                #pragma unroll
                for (int r = 0; r < 4; r++) sfr[mt][n][r] = 0.f;

        #pragma unroll
        for (int n = 0; n < 4; n++) {
            #pragma unroll
            for (int ks = 0; ks < 2; ks++) {
                uint32_t bhi[2], blo[2];
                bhi[0] = Ksh[bufc][0][ks*8 + j][n*8 + g];
                bhi[1] = Ksh[bufc][0][ks*8 + j + 4][n*8 + g];
                blo[0] = Ksh[bufc][1][ks*8 + j][n*8 + g];
                blo[1] = Ksh[bufc][1][ks*8 + j + 4][n*8 + g];
                #pragma unroll
                for (int mt = 0; mt < 2; mt++) {
                    mma_bf16(sfr[mt][n], qh[mt][ks], bhi);
                    mma_bf16(sfr[mt][n], ql[mt][ks], bhi);
                    mma_bf16(sfr[mt][n], qh[mt][ks], blo);
                }
            }
        }

        // ---- softmax, exp2 domain: p = ex2(fm*(s2 + mk) + cb) ----
        uint32_t phr0[2][4], phr1[2][4], plr0[2][4], plr1[2][4];
        #pragma unroll
        for (int mt = 0; mt < 2; mt++) {
            float f0 = fm[mt][0], f1 = fm[mt][1];
            float c0 = cb[mt][0], c1 = cb[mt][1];
            float ls0 = 0.f, ls1 = 0.f;
            #pragma unroll
            for (int n = 0; n < 4; n++) {
                float mk0 = sMask[bufc][n*8 + 2*j];
                float mk1 = sMask[bufc][n*8 + 2*j + 1];
                float p0 = ex2f(fmaf(f0, sfr[mt][n][0] + mk0, c0));
                float p1 = ex2f(fmaf(f0, sfr[mt][n][1] + mk1, c0));
                float p2 = ex2f(fmaf(f1, sfr[mt][n][2] + mk0, c1));
                float p3 = ex2f(fmaf(f1, sfr[mt][n][3] + mk1, c1));
                ls0 += p0 + p1; ls1 += p2 + p3;
                uint32_t h01 = pack_bf16x2(p0, p1);
                uint32_t h23 = pack_bf16x2(p2, p3);
                phr0[mt][n] = h01;
                phr1[mt][n] = h23;
                plr0[mt][n] = pack_bf16x2(p0 - bf_low(h01), p1 - bf_high(h01));
                plr1[mt][n] = pack_bf16x2(p2 - bf_low(h23), p3 - bf_high(h23));
            }
            lrow[mt][0] += ls0; lrow[mt][1] += ls1;
        }

        #pragma unroll
        for (int nd = 0; nd < 4; nd++) {
            #pragma unroll
            for (int k2 = 0; k2 < 2; k2++) {
                uint32_t bhi[2], blo[2];
                bhi[0] = Vsh[bufc][0][nd*8 + g][k2*8 + j];
                bhi[1] = Vsh[bufc][0][nd*8 + g][k2*8 + j + 4];
                blo[0] = Vsh[bufc][1][nd*8 + g][k2*8 + j];
                blo[1] = Vsh[bufc][1][nd*8 + g][k2*8 + j + 4];
                #pragma unroll
                for (int mt = 0; mt < 2; mt++) {
                    uint32_t ahi[4] = {phr0[mt][2*k2], phr1[mt][2*k2],
                                       phr0[mt][2*k2+1], phr1[mt][2*k2+1]};
                    uint32_t alo[4] = {plr0[mt][2*k2], plr1[mt][2*k2],
                                       plr0[mt][2*k2+1], plr1[mt][2*k2+1]};
                    mma_bf16(ofr[mt][nd], ahi, bhi);
                    mma_bf16(ofr[mt][nd], ahi, blo);
                    mma_bf16(ofr[mt][nd], alo, bhi);
                }
            }
        }

        if (it + 1 < NIT) {
            int bufn = bufc ^ 1;
            *(uint4*)&Ksh[bufn][0][kdp][kkg] = rkh;
            *(uint4*)&Ksh[bufn][1][kdp][kkg] = rkl;
            *(uint4*)&Vsh[bufn][0][vdm][vpg] = rvh;
            *(uint4*)&Vsh[bufn][1][vdm][vpg] = rvl;
            if (tid < KT) sMask[bufn][tid] = (1.0f - ml) * NEGF;
        }
        __syncthreads();
    }

    #pragma unroll
    for (int mt = 0; mt < 2; mt++) {
        float l0 = lrow[mt][0], l1 = lrow[mt][1];
        l0 += __shfl_xor_sync(0xffffffffu, l0, 1);
        l0 += __shfl_xor_sync(0xffffffffu, l0, 2);
        l1 += __shfl_xor_sync(0xffffffffu, l1, 1);
        l1 += __shfl_xor_sync(0xffffffffu, l1, 2);
        float inv0 = 1.0f / l0, inv1 = 1.0f / l1;
        int r0 = q0 + mt*16 + g;
        #pragma unroll
        for (int nd = 0; nd < 4; nd++) {
            int col = h*DH + nd*8 + 2*j;
            float2 v0 = make_float2(ofr[mt][nd][0]*inv0, ofr[mt][nd][1]*inv0);
            float2 v1 = make_float2(ofr[mt][nd][2]*inv1, ofr[mt][nd][3]*inv1);
            *(float2*)(go + ((size_t)b*SEQ + r0)*DM + col)     = v0;
            *(float2*)(go + ((size_t)b*SEQ + r0 + 8)*DM + col) = v1;
        }
    }
}

// ================= launch =================
extern "C" void kernel_launch(void* const* d_in, const int* in_sizes, int n_in,
                              void* d_out, int out_size) {
    const float* x    = (const float*)d_in[0];
    const float* mask = (const float*)d_in[1];
    const float* Wq   = (const float*)d_in[2];
    const float* Wk   = (const float*)d_in[3];
    const float* Wv   = (const float*)d_in[4];
    const float* Wo   = (const float*)d_in[5];
    const float* W1   = (const float*)d_in[6];
    const float* b1   = (const float*)d_in[7];
    const float* W2   = (const float*)d_in[8];
    const float* b2   = (const float*)d_in[9];
    float* out = (float*)d_out;

    float *qkv_p, *o_p, *xc_p, *ff_p;
    uint32_t *pqkh, *pqkl, *pwoh, *pwol, *pw1h, *pw1l, *pw2h, *pw2l;
    cudaGetSymbolAddress((void**)&qkv_p, g_qkv);
    cudaGetSymbolAddress((void**)&o_p,   g_obuf);
    cudaGetSymbolAddress((void**)&xc_p,  g_xc);
    cudaGetSymbolAddress((void**)&ff_p,  g_ff);
    cudaGetSymbolAddress((void**)&pqkh,  g_pwqkv_h);
    cudaGetSymbolAddress((void**)&pqkl,  g_pwqkv_l);
    cudaGetSymbolAddress((void**)&pwoh,  g_pwo_h);
    cudaGetSymbolAddress((void**)&pwol,  g_pwo_l);
    cudaGetSymbolAddress((void**)&pw1h,  g_pw1_h);
    cudaGetSymbolAddress((void**)&pw1l,  g_pw1_l);
    cudaGetSymbolAddress((void**)&pw2h,  g_pw2_h);
    cudaGetSymbolAddress((void**)&pw2l,  g_pw2_l);

    const int SMEM_GEMM = (2*2*GBM*APAD + 2*2*GBN*APAD) * 4;
    cudaFuncSetAttribute(gemm_mma, cudaFuncAttributeMaxDynamicSharedMemorySize, SMEM_GEMM);

    pack_qkv<<<(NL*3*DM*(DM/2) + 255)/256, 256>>>(Wq, Wk, Wv);
    pack_w<<<(NL*DM*(DM/2) + 255)/256, 256>>>(Wo, pwoh, pwol, DM, DM);
    pack_w<<<(NL*DF*(DM/2) + 255)/256, 256>>>(W1, pw1h, pw1l, DM, DF);
    pack_w<<<(NL*DM*(DF/2) + 255)/256, 256>>>(W2, pw2h, pw2l, DF, DM);

    const size_t QKV_STRIDE = (size_t)MR * DM;

    for (int n = 0; n < NL; n++) {
        const float* xin = (n == 0) ? x : xc_p;

        gemm_mma<<<dim3(DM/GBN, MR/GBM, 3), 256, SMEM_GEMM>>>(
            xin, pqkh + (size_t)n*3*DM*(DM/2), pqkl + (size_t)n*3*DM*(DM/2),
            nullptr, nullptr, qkv_p, MR, DM, DM, 0);

        pack_kv<<<dim3(SEQ/32, NB*NH, 2), dim3(32, 8)>>>(
            qkv_p + QKV_STRIDE, qkv_p + 2*QKV_STRIDE);

        attn_mma<<<dim3(SEQ/128, NB*NH), 128>>>(qkv_p, mask, o_p);

        gemm_mma<<<dim3(DM/GBN, MR/GBM, 1), 256, SMEM_GEMM>>>(
            o_p, pwoh + (size_t)n*DM*(DM/2), pwol + (size_t)n*DM*(DM/2),
            nullptr, xin, xc_p, MR, DM, DM, 1);

        gemm_mma<<<dim3(DF/GBN, MR/GBM, 1), 256, SMEM_GEMM>>>(
            xc_p, pw1h + (size_t)n*DF*(DM/2), pw1l + (size_t)n*DF*(DM/2),
            b1 + (size_t)n*DF, nullptr, ff_p, MR, DF, DM, 2);

        float* dst = (n == NL - 1) ? out : xc_p;
        gemm_mma<<<dim3(DM/GBN, MR/GBM, 1), 256, SMEM_GEMM>>>(
            ff_p, pw2h + (size_t)n*DM*(DF/2), pw2l + (size_t)n*DM*(DF/2),
            b2 + (size_t)n*DM, xc_p, dst, MR, DM, DF, 3);
    }
}

// round 11
// speedup vs baseline: 1.1048x; 1.1048x over previous
#include <cuda_runtime.h>
#include <math.h>
#include <stdint.h>

#define NL   4
#define NB   4
#define SEQ  2048
#define DM   256
#define NH   8
#define DH   32
#define DF   512
#define MR   (NB*SEQ)

#define NEGF (-3.402823466e38f)
#define L2E  1.44269504088896340736f

typedef unsigned long long u64;

// ================= bf16 helpers =================
__device__ __forceinline__ uint32_t pack_bf16x2(float lo, float hi) {
    uint32_t r; asm("cvt.rn.bf16x2.f32 %0, %1, %2;" : "=r"(r) : "f"(hi), "f"(lo)); return r;
}
__device__ __forceinline__ float bf_low(uint32_t p)  { return __uint_as_float(p << 16); }
__device__ __forceinline__ float bf_high(uint32_t p) { return __uint_as_float(p & 0xffff0000u); }
__device__ __forceinline__ float ex2f(float x) {
    float r; asm("ex2.approx.f32 %0, %1;" : "=f"(r) : "f"(x)); return r;
}

__device__ __forceinline__ void mma_bf16(float* c, const uint32_t* a, const uint32_t* b) {
    asm volatile(
        "mma.sync.aligned.m16n8k16.row.col.f32.bf16.bf16.f32 "
        "{%0,%1,%2,%3},{%4,%5,%6,%7},{%8,%9},{%0,%1,%2,%3};"
        : "+f"(c[0]), "+f"(c[1]), "+f"(c[2]), "+f"(c[3])
        : "r"(a[0]), "r"(a[1]), "r"(a[2]), "r"(a[3]), "r"(b[0]), "r"(b[1]));
}

// ================= scratch =================
__device__ float g_qkv [3*(size_t)MR*DM];
__device__ float g_obuf[(size_t)MR*DM];
__device__ float g_xc  [(size_t)MR*DM];
__device__ float g_ff  [(size_t)MR*DF];

// packed K: [bh][dim-pair 16][key 2048] hi/lo;  packed V: [bh][dim 32][key-pair 1024] hi/lo
__device__ uint32_t g_kph[NB*NH*16*SEQ];
__device__ uint32_t g_kpl[NB*NH*16*SEQ];
__device__ uint32_t g_vph[NB*NH*32*(SEQ/2)];
__device__ uint32_t g_vpl[NB*NH*32*(SEQ/2)];
__device__ unsigned g_kmax2[NB*NH];        // max ||k||^2 per (b,h), float bits

// packed bf16 hi/lo weights
__device__ uint32_t g_pwqkv_h[NL*3*DM*(DM/2)];
__device__ uint32_t g_pwqkv_l[NL*3*DM*(DM/2)];
__device__ uint32_t g_pwo_h  [NL*DM*(DM/2)];
__device__ uint32_t g_pwo_l  [NL*DM*(DM/2)];
__device__ uint32_t g_pw1_h  [NL*DF*(DM/2)];
__device__ uint32_t g_pw1_l  [NL*DF*(DM/2)];
__device__ uint32_t g_pw2_h  [NL*DM*(DF/2)];
__device__ uint32_t g_pw2_l  [NL*DM*(DF/2)];

// ================= weight packing =================
__global__ void pack_qkv(const float* __restrict__ Wq,
                         const float* __restrict__ Wk,
                         const float* __restrict__ Wv) {
    int i = blockIdx.x * blockDim.x + threadIdx.x;
    const int PER_M = DM * (DM/2);
    const int TOT = NL * 3 * PER_M;
    if (i >= TOT) return;
    int l  = i / (3*PER_M);
    int r  = i % (3*PER_M);
    int m  = r / PER_M;
    int r2 = r % PER_M;
    int n  = r2 >> 7;
    int kp = r2 & 127;
    int h = n >> 5, e = n & 31;
    const float* W = (m == 0) ? Wq : (m == 1) ? Wk : Wv;
    size_t s0 = (((size_t)l*NH + h)*DM + 2*kp)*DH + e;
    float v0 = W[s0], v1 = W[s0 + DH];
    uint32_t hp = pack_bf16x2(v0, v1);
    g_pwqkv_h[i] = hp;
    g_pwqkv_l[i] = pack_bf16x2(v0 - bf_low(hp), v1 - bf_high(hp));
}

__global__ void pack_w(const float* __restrict__ W, uint32_t* __restrict__ dh,
                       uint32_t* __restrict__ dl, int K, int N) {
    int i = blockIdx.x * blockDim.x + threadIdx.x;
    int per = N * (K >> 1);
    if (i >= NL * per) return;
    int l = i / per, r = i % per;
    int n = r / (K >> 1), kp = r % (K >> 1);
    size_t s = (size_t)l*K*N + (size_t)(2*kp)*N + n;
    float v0 = W[s], v1 = W[s + N];
    uint32_t hp = pack_bf16x2(v0, v1);
    dh[i] = hp;
    dl[i] = pack_bf16x2(v0 - bf_low(hp), v1 - bf_high(hp));
}

// ================= K/V transpose + split-bf16 pack (+ K norm max) ==========
__global__ void pack_kv(const float* __restrict__ k, const float* __restrict__ v) {
    __shared__ float tl[32][33];
    int bh = blockIdx.y;
    int b = bh >> 3, h = bh & 7;
    int l0 = blockIdx.x * 32;
    const float* src = (blockIdx.z == 0) ? k : v;
    #pragma unroll
    for (int kk = 0; kk < 4; kk++) {
        int l = l0 + threadIdx.y + kk*8;
        tl[threadIdx.y + kk*8][threadIdx.x] = src[((size_t)b*SEQ + l)*DM + h*32 + threadIdx.x];
    }
    __syncthreads();
    if (blockIdx.z == 0) {
        #pragma unroll
        for (int kk = 0; kk < 2; kk++) {
            int dp = threadIdx.y + kk*8;
            float v0 = tl[threadIdx.x][2*dp], v1 = tl[threadIdx.x][2*dp+1];
            uint32_t hp = pack_bf16x2(v0, v1);
            size_t o = ((size_t)bh*16 + dp)*SEQ + l0 + threadIdx.x;
            g_kph[o] = hp;
            g_kpl[o] = pack_bf16x2(v0 - bf_low(hp), v1 - bf_high(hp));
        }
        if (threadIdx.y == 0) {
            float n2 = 0.f;
            #pragma unroll
            for (int e = 0; e < 32; e++) n2 = fmaf(tl[threadIdx.x][e], tl[threadIdx.x][e], n2);
            #pragma unroll
            for (int d = 16; d > 0; d >>= 1)
                n2 = fmaxf(n2, __shfl_xor_sync(0xffffffffu, n2, d));
            if (threadIdx.x == 0)
                atomicMax(&g_kmax2[bh], __float_as_uint(n2));
        }
    } else {
        #pragma unroll
        for (int kk = 0; kk < 2; kk++) {
            int idx = threadIdx.y*32 + threadIdx.x + kk*256;
            int e = idx >> 4, lp = idx & 15;
            float v0 = tl[2*lp][e], v1 = tl[2*lp+1][e];
            uint32_t hp = pack_bf16x2(v0, v1);
            size_t o = ((size_t)bh*32 + e)*(SEQ/2) + (l0 >> 1) + lp;
            g_vph[o] = hp;
            g_vpl[o] = pack_bf16x2(v0 - bf_low(hp), v1 - bf_high(hp));
        }
    }
}

// ================= HMMA GEMM (bf16 3-term, double-buffered) =================
#define GBM 128
#define GBN 64
#define GBK 32
#define AKP (GBK/2)
#define APAD 20

__device__ __forceinline__ float gelu_exact(float x) {
    return 0.5f * x * (1.0f + erff(x * 0.70710678118654752440f));
}

__device__ __forceinline__ void epi2(float* C, size_t off, float c0, float c1,
                                     float2 bb, const float* res, int mode) {
    float2 o;
    if (mode == 1) {
        float2 r = *(const float2*)(res + off);
        o.x = (c0 + r.x)*0.5f; o.y = (c1 + r.y)*0.5f;
    } else if (mode == 2) {
        o.x = gelu_exact(c0 + bb.x); o.y = gelu_exact(c1 + bb.y);
    } else if (mode == 3) {
        float2 r = *(const float2*)(res + off);
        o.x = (c0 + bb.x + r.x)*0.5f; o.y = (c1 + bb.y + r.y)*0.5f;
    } else {
        o.x = c0; o.y = c1;
    }
    *(float2*)(C + off) = o;
}

extern __shared__ uint32_t dsm[];

__global__ __launch_bounds__(256, 2)
void gemm_mma(const float* __restrict__ A, const uint32_t* __restrict__ Bh,
              const uint32_t* __restrict__ Bl, const float* __restrict__ bias,
              const float* __restrict__ res, float* __restrict__ C,
              int M, int N, int K, int mode) {
    uint32_t* Ash = dsm;
    uint32_t* Bsh = dsm + 2*2*GBM*APAD;

    if (mode == 0) {
        int z = blockIdx.z;
        Bh += (size_t)z * DM * (DM/2);
        Bl += (size_t)z * DM * (DM/2);
        C  += (size_t)z * (size_t)M * N;
        // fold kmax reset into QKV GEMM (runs before pack_kv in-stream)
        if (blockIdx.x == 0 && blockIdx.y == 0 && z == 0 && threadIdx.x < NB*NH)
            g_kmax2[threadIdx.x] = 0u;
    }
    int bm = blockIdx.y * GBM;
    int bn = blockIdx.x * GBN;
    int tid = threadIdx.x;
    int warp = tid >> 5, lane = tid & 31;
    int g = lane >> 2, j = lane & 3;
    int wm = (warp & 3) * 32;
    int wn = (warp >> 2) * 32;
    int ldkp = K >> 1;

    int arow = tid >> 3;
    int akp0 = (tid & 7) * 2;
    int bn0  = tid >> 2;
    int bkp0 = (tid & 3) * 4;

    const float* ap[4];
    #pragma unroll
    for (int s = 0; s < 4; s++)
        ap[s] = A + (size_t)(bm + arow + 32*s)*K + (tid & 7)*4;
    const uint32_t* bph = Bh + (size_t)(bn + bn0)*ldkp + bkp0;
    const uint32_t* bpl = Bl + (size_t)(bn + bn0)*ldkp + bkp0;

    float acc[2][4][4];
    #pragma unroll
    for (int mt = 0; mt < 2; mt++)
        #pragma unroll
        for (int n = 0; n < 4; n++)
            #pragma unroll
            for (int r = 0; r < 4; r++) acc[mt][n][r] = 0.f;

    int nt = K / GBK;
    float4 af[4]; uint4 bfh, bfl;
    #pragma unroll
    for (int s = 0; s < 4; s++) af[s] = *(const float4*)ap[s];
    bfh = *(const uint4*)bph;
    bfl = *(const uint4*)bpl;

    {
        #pragma unroll
        for (int s = 0; s < 4; s++) {
            float4 v = af[s];
            uint32_t h0 = pack_bf16x2(v.x, v.y);
            uint32_t h1 = pack_bf16x2(v.z, v.w);
            uint32_t l0 = pack_bf16x2(v.x - bf_low(h0), v.y - bf_high(h0));
            uint32_t l1 = pack_bf16x2(v.z - bf_low(h1), v.w - bf_high(h1));
            int row = arow + 32*s;
            uint32_t* ph = Ash + row*APAD + akp0;
            uint32_t* pl = Ash + GBM*APAD + row*APAD + akp0;
            ph[0] = h0; ph[1] = h1; pl[0] = l0; pl[1] = l1;
        }
        uint32_t* ph = Bsh + bn0*APAD + bkp0;
        uint32_t* pl = Bsh + GBN*APAD + bn0*APAD + bkp0;
        ph[0]=bfh.x; ph[1]=bfh.y; ph[2]=bfh.z; ph[3]=bfh.w;
        pl[0]=bfl.x; pl[1]=bfl.y; pl[2]=bfl.z; pl[3]=bfl.w;
    }
    __syncthreads();

    for (int t = 0; t < nt; t++) {
        int buf = t & 1;
        if (t + 1 < nt) {
            int k0 = (t+1)*GBK;
            #pragma unroll
            for (int s = 0; s < 4; s++) af[s] = *(const float4*)(ap[s] + k0);
            bfh = *(const uint4*)(bph + (t+1)*AKP);
            bfl = *(const uint4*)(bpl + (t+1)*AKP);
        }

        const uint32_t* Ab = Ash + buf*2*GBM*APAD;
        const uint32_t* Bb = Bsh + buf*2*GBN*APAD;
        #pragma unroll
        for (int kc = 0; kc < 2; kc++) {
            uint32_t ah[2][4], al[2][4];
            #pragma unroll
            for (int mt = 0; mt < 2; mt++) {
                int r0 = wm + mt*16 + g;
                const uint32_t* pa  = Ab;
                const uint32_t* pal = Ab + GBM*APAD;
                ah[mt][0] = pa [(r0)  *APAD + kc*8 + j];
                ah[mt][1] = pa [(r0+8)*APAD + kc*8 + j];
                ah[mt][2] = pa [(r0)  *APAD + kc*8 + j + 4];
                ah[mt][3] = pa [(r0+8)*APAD + kc*8 + j + 4];
                al[mt][0] = pal[(r0)  *APAD + kc*8 + j];
                al[mt][1] = pal[(r0+8)*APAD + kc*8 + j];
                al[mt][2] = pal[(r0)  *APAD + kc*8 + j + 4];
                al[mt][3] = pal[(r0+8)*APAD + kc*8 + j + 4];
            }
            #pragma unroll
            for (int n = 0; n < 4; n++) {
                int c0 = wn + n*8 + g;
                uint32_t bh2[2], bl2[2];
                bh2[0] = Bb[c0*APAD + kc*8 + j];
                bh2[1] = Bb[c0*APAD + kc*8 + j + 4];
                bl2[0] = Bb[GBN*APAD + c0*APAD + kc*8 + j];
                bl2[1] = Bb[GBN*APAD + c0*APAD + kc*8 + j + 4];
                #pragma unroll
                for (int mt = 0; mt < 2; mt++) {
                    mma_bf16(acc[mt][n], ah[mt], bh2);
                    mma_bf16(acc[mt][n], al[mt], bh2);
                    mma_bf16(acc[mt][n], ah[mt], bl2);
                }
            }
        }

        if (t + 1 < nt) {
            int nb = buf ^ 1;
            uint32_t* An = Ash + nb*2*GBM*APAD;
            uint32_t* Bn = Bsh + nb*2*GBN*APAD;
            #pragma unroll
            for (int s = 0; s < 4; s++) {
                float4 v = af[s];
                uint32_t h0 = pack_bf16x2(v.x, v.y);
                uint32_t h1 = pack_bf16x2(v.z, v.w);
                uint32_t l0 = pack_bf16x2(v.x - bf_low(h0), v.y - bf_high(h0));
                uint32_t l1 = pack_bf16x2(v.z - bf_low(h1), v.w - bf_high(h1));
                int row = arow + 32*s;
                uint32_t* ph = An + row*APAD + akp0;
                uint32_t* pl = An + GBM*APAD + row*APAD + akp0;
                ph[0] = h0; ph[1] = h1; pl[0] = l0; pl[1] = l1;
            }
            uint32_t* ph = Bn + bn0*APAD + bkp0;
            uint32_t* pl = Bn + GBN*APAD + bn0*APAD + bkp0;
            ph[0]=bfh.x; ph[1]=bfh.y; ph[2]=bfh.z; ph[3]=bfh.w;
            pl[0]=bfl.x; pl[1]=bfl.y; pl[2]=bfl.z; pl[3]=bfl.w;
        }
        __syncthreads();
    }

    float2 bb[4];
    #pragma unroll
    for (int n = 0; n < 4; n++) {
        if (mode == 2 || mode == 3)
            bb[n] = *(const float2*)(bias + bn + wn + n*8 + 2*j);
        else
            bb[n] = make_float2(0.f, 0.f);
    }
    #pragma unroll
    for (int mt = 0; mt < 2; mt++) {
        int r0 = bm + wm + mt*16 + g;
        #pragma unroll
        for (int n = 0; n < 4; n++) {
            int col = bn + wn + n*8 + 2*j;
            size_t o0 = (size_t)r0*N + col;
            size_t o1 = (size_t)(r0 + 8)*N + col;
            epi2(C, o0, acc[mt][n][0], acc[mt][n][1], bb[n], res, mode);
            epi2(C, o1, acc[mt][n][2], acc[mt][n][3], bb[n], res, mode);
        }
    }
}

// ================= warp-MMA flash attention (static bound, exp2, occ3) ======
#define KT  32
#define NIT (SEQ/KT)

__global__ __launch_bounds__(128, 3)
void attn_mma(const float* __restrict__ gq, const float* __restrict__ gmask,
              float* __restrict__ go) {
    __shared__ __align__(16) uint32_t Ksh[2][2][16][40];
    __shared__ __align__(16) uint32_t Vsh[2][2][32][20];
    __shared__ float sMask[2][KT];   // stores (1-mk)*NEGF

    int tid  = threadIdx.x;
    int warp = tid >> 5;
    int lane = tid & 31;
    int g    = lane >> 2;
    int j    = lane & 3;
    int bh   = blockIdx.y;
    int b    = bh >> 3, h = bh & 7;
    int q0   = blockIdx.x * 128 + warp * 32;

    // Q fragments, pre-scaled by log2(e) so softmax runs in ex2 domain
    uint32_t qh[2][2][4], ql[2][2][4];
    float qn2[2][2] = {};
    #pragma unroll
    for (int mt = 0; mt < 2; mt++) {
        #pragma unroll
        for (int rr = 0; rr < 2; rr++) {
            int row = q0 + mt*16 + g + rr*8;
            const float* qp = gq + ((size_t)b*SEQ + row)*DM + h*DH;
            #pragma unroll
            for (int u = 0; u < 4; u++) {
                float2 v = *(const float2*)(qp + u*8 + 2*j);
                v.x *= L2E; v.y *= L2E;
                qn2[mt][rr] = fmaf(v.x, v.x, fmaf(v.y, v.y, qn2[mt][rr]));
                uint32_t hp = pack_bf16x2(v.x, v.y);
                uint32_t lp = pack_bf16x2(v.x - bf_low(hp), v.y - bf_high(hp));
                qh[mt][u>>1][rr + 2*(u&1)] = hp;
                ql[mt][u>>1][rr + 2*(u&1)] = lp;
            }
        }
    }
    #pragma unroll
    for (int mt = 0; mt < 2; mt++)
        #pragma unroll
        for (int rr = 0; rr < 2; rr++) {
            qn2[mt][rr] += __shfl_xor_sync(0xffffffffu, qn2[mt][rr], 1);
            qn2[mt][rr] += __shfl_xor_sync(0xffffffffu, qn2[mt][rr], 2);
        }

    // |q*L2E| * |k| bounds s*log2e; +43.28 = 30*log2e slack
    float kmaxn = sqrtf(__uint_as_float(g_kmax2[bh]));
    float fm[2][2], cb[2][2];
    #pragma unroll
    for (int mt = 0; mt < 2; mt++) {
        fm[mt][0] = gmask[b*SEQ + q0 + mt*16 + g];
        fm[mt][1] = gmask[b*SEQ + q0 + mt*16 + g + 8];
        #pragma unroll
        for (int rr = 0; rr < 2; rr++)
            cb[mt][rr] = (fm[mt][rr] == 0.f) ? 0.f
                       : -(sqrtf(qn2[mt][rr]) * kmaxn - 43.2808512266689f);
    }

    float lrow[2][2], ofr[2][4][4];
    #pragma unroll
    for (int mt = 0; mt < 2; mt++) {
        lrow[mt][0] = 0.f; lrow[mt][1] = 0.f;
        #pragma unroll
        for (int nd = 0; nd < 4; nd++)
            #pragma unroll
            for (int r = 0; r < 4; r++) ofr[mt][nd][r] = 0.f;
    }

    int kdp = tid >> 3;
    int kkg = (tid & 7) * 4;
    int vdm = tid >> 2;
    int vpg = (tid & 3) * 4;
    const uint32_t* kbh = g_kph + ((size_t)bh*16 + kdp)*SEQ + kkg;
    const uint32_t* kbl = g_kpl + ((size_t)bh*16 + kdp)*SEQ + kkg;
    const uint32_t* vbh = g_vph + ((size_t)bh*32 + vdm)*(SEQ/2) + vpg;
    const uint32_t* vbl = g_vpl + ((size_t)bh*32 + vdm)*(SEQ/2) + vpg;
    const float* mbase = gmask + b*SEQ + tid;

    uint4 rkh, rkl, rvh, rvl; float ml = 0.f;
    rkh = *(const uint4*)(kbh);
    rkl = *(const uint4*)(kbl);
    rvh = *(const uint4*)(vbh);
    rvl = *(const uint4*)(vbl);
    if (tid < KT) ml = *mbase;

    *(uint4*)&Ksh[0][0][kdp][kkg] = rkh;
    *(uint4*)&Ksh[0][1][kdp][kkg] = rkl;
    *(uint4*)&Vsh[0][0][vdm][vpg] = rvh;
    *(uint4*)&Vsh[0][1][vdm][vpg] = rvl;
    if (tid < KT) sMask[0][tid] = (1.0f - ml) * NEGF;
    __syncthreads();

    for (int it = 0; it < NIT; it++) {
        int bufc = it & 1;
        if (it + 1 < NIT) {
            rkh = *(const uint4*)(kbh + (it+1)*KT);
            rkl = *(const uint4*)(kbl + (it+1)*KT);
            rvh = *(const uint4*)(vbh + (it+1)*(KT/2));
            rvl = *(const uint4*)(vbl + (it+1)*(KT/2));
            if (tid < KT) ml = mbase[(it+1)*KT];
        }

        float sfr[2][4][4];
        #pragma unroll
        for (int mt = 0; mt < 2; mt++)
            #pragma unroll
            for (int n = 0; n < 4; n++)
                #pragma unroll
                for (int r = 0; r < 4; r++) sfr[mt][n][r] = 0.f;

        #pragma unroll
        for (int n = 0; n < 4; n++) {
            #pragma unroll
            for (int ks = 0; ks < 2; ks++) {
                uint32_t bhi[2], blo[2];
                bhi[0] = Ksh[bufc][0][ks*8 + j][n*8 + g];
                bhi[1] = Ksh[bufc][0][ks*8 + j + 4][n*8 + g];
                blo[0] = Ksh[bufc][1][ks*8 + j][n*8 + g];
                blo[1] = Ksh[bufc][1][ks*8 + j + 4][n*8 + g];
                #pragma unroll
                for (int mt = 0; mt < 2; mt++) {
                    mma_bf16(sfr[mt][n], qh[mt][ks], bhi);
                    mma_bf16(sfr[mt][n], ql[mt][ks], bhi);
                    mma_bf16(sfr[mt][n], qh[mt][ks], blo);
                }
            }
        }

        // ---- softmax, exp2 domain: p = ex2(fm*(s2 + mk) + cb) ----
        uint32_t phr0[2][4], phr1[2][4], plr0[2][4], plr1[2][4];
        #pragma unroll
        for (int mt = 0; mt < 2; mt++) {
            float f0 = fm[mt][0], f1 = fm[mt][1];
            float c0 = cb[mt][0], c1 = cb[mt][1];
            float ls0 = 0.f, ls1 = 0.f;
            #pragma unroll
            for (int n = 0; n < 4; n++) {
                float mk0 = sMask[bufc][n*8 + 2*j];
                float mk1 = sMask[bufc][n*8 + 2*j + 1];
                float p0 = ex2f(fmaf(f0, sfr[mt][n][0] + mk0, c0));
                float p1 = ex2f(fmaf(f0, sfr[mt][n][1] + mk1, c0));
                float p2 = ex2f(fmaf(f1, sfr[mt][n][2] + mk0, c1));
                float p3 = ex2f(fmaf(f1, sfr[mt][n][3] + mk1, c1));
                ls0 += p0 + p1; ls1 += p2 + p3;
                uint32_t h01 = pack_bf16x2(p0, p1);
                uint32_t h23 = pack_bf16x2(p2, p3);
                phr0[mt][n] = h01;
                phr1[mt][n] = h23;
                plr0[mt][n] = pack_bf16x2(p0 - bf_low(h01), p1 - bf_high(h01));
                plr1[mt][n] = pack_bf16x2(p2 - bf_low(h23), p3 - bf_high(h23));
            }
            lrow[mt][0] += ls0; lrow[mt][1] += ls1;
        }

        #pragma unroll
        for (int nd = 0; nd < 4; nd++) {
            #pragma unroll
            for (int k2 = 0; k2 < 2; k2++) {
                uint32_t bhi[2], blo[2];
                bhi[0] = Vsh[bufc][0][nd*8 + g][k2*8 + j];
                bhi[1] = Vsh[bufc][0][nd*8 + g][k2*8 + j + 4];
                blo[0] = Vsh[bufc][1][nd*8 + g][k2*8 + j];
                blo[1] = Vsh[bufc][1][nd*8 + g][k2*8 + j + 4];
                #pragma unroll
                for (int mt = 0; mt < 2; mt++) {
                    uint32_t ahi[4] = {phr0[mt][2*k2], phr1[mt][2*k2],
                                       phr0[mt][2*k2+1], phr1[mt][2*k2+1]};
                    uint32_t alo[4] = {plr0[mt][2*k2], plr1[mt][2*k2],
                                       plr0[mt][2*k2+1], plr1[mt][2*k2+1]};
                    mma_bf16(ofr[mt][nd], ahi, bhi);
                    mma_bf16(ofr[mt][nd], ahi, blo);
                    mma_bf16(ofr[mt][nd], alo, bhi);
                }
            }
        }

        if (it + 1 < NIT) {
            int bufn = bufc ^ 1;
            *(uint4*)&Ksh[bufn][0][kdp][kkg] = rkh;
            *(uint4*)&Ksh[bufn][1][kdp][kkg] = rkl;
            *(uint4*)&Vsh[bufn][0][vdm][vpg] = rvh;
            *(uint4*)&Vsh[bufn][1][vdm][vpg] = rvl;
            if (tid < KT) sMask[bufn][tid] = (1.0f - ml) * NEGF;
        }
        __syncthreads();
    }

    #pragma unroll
    for (int mt = 0; mt < 2; mt++) {
        float l0 = lrow[mt][0], l1 = lrow[mt][1];
        l0 += __shfl_xor_sync(0xffffffffu, l0, 1);
        l0 += __shfl_xor_sync(0xffffffffu, l0, 2);
        l1 += __shfl_xor_sync(0xffffffffu, l1, 1);
        l1 += __shfl_xor_sync(0xffffffffu, l1, 2);
        float inv0 = 1.0f / l0, inv1 = 1.0f / l1;
        int r0 = q0 + mt*16 + g;
        #pragma unroll
        for (int nd = 0; nd < 4; nd++) {
            int col = h*DH + nd*8 + 2*j;
            float2 v0 = make_float2(ofr[mt][nd][0]*inv0, ofr[mt][nd][1]*inv0);
            float2 v1 = make_float2(ofr[mt][nd][2]*inv1, ofr[mt][nd][3]*inv1);
            *(float2*)(go + ((size_t)b*SEQ + r0)*DM + col)     = v0;
            *(float2*)(go + ((size_t)b*SEQ + r0 + 8)*DM + col) = v1;
        }
    }
}

// ================= launch =================
extern "C" void kernel_launch(void* const* d_in, const int* in_sizes, int n_in,
                              void* d_out, int out_size) {
    const float* x    = (const float*)d_in[0];
    const float* mask = (const float*)d_in[1];
    const float* Wq   = (const float*)d_in[2];
    const float* Wk   = (const float*)d_in[3];
    const float* Wv   = (const float*)d_in[4];
    const float* Wo   = (const float*)d_in[5];
    const float* W1   = (const float*)d_in[6];
    const float* b1   = (const float*)d_in[7];
    const float* W2   = (const float*)d_in[8];
    const float* b2   = (const float*)d_in[9];
    float* out = (float*)d_out;

    float *qkv_p, *o_p, *xc_p, *ff_p;
    uint32_t *pqkh, *pqkl, *pwoh, *pwol, *pw1h, *pw1l, *pw2h, *pw2l;
    cudaGetSymbolAddress((void**)&qkv_p, g_qkv);
    cudaGetSymbolAddress((void**)&o_p,   g_obuf);
    cudaGetSymbolAddress((void**)&xc_p,  g_xc);
    cudaGetSymbolAddress((void**)&ff_p,  g_ff);
    cudaGetSymbolAddress((void**)&pqkh,  g_pwqkv_h);
    cudaGetSymbolAddress((void**)&pqkl,  g_pwqkv_l);
    cudaGetSymbolAddress((void**)&pwoh,  g_pwo_h);
    cudaGetSymbolAddress((void**)&pwol,  g_pwo_l);
    cudaGetSymbolAddress((void**)&pw1h,  g_pw1_h);
    cudaGetSymbolAddress((void**)&pw1l,  g_pw1_l);
    cudaGetSymbolAddress((void**)&pw2h,  g_pw2_h);
    cudaGetSymbolAddress((void**)&pw2l,  g_pw2_l);

    const int SMEM_GEMM = (2*2*GBM*APAD + 2*2*GBN*APAD) * 4;
    cudaFuncSetAttribute(gemm_mma, cudaFuncAttributeMaxDynamicSharedMemorySize, SMEM_GEMM);

    pack_qkv<<<(NL*3*DM*(DM/2) + 255)/256, 256>>>(Wq, Wk, Wv);
    pack_w<<<(NL*DM*(DM/2) + 255)/256, 256>>>(Wo, pwoh, pwol, DM, DM);
    pack_w<<<(NL*DF*(DM/2) + 255)/256, 256>>>(W1, pw1h, pw1l, DM, DF);
    pack_w<<<(NL*DM*(DF/2) + 255)/256, 256>>>(W2, pw2h, pw2l, DF, DM);

    const size_t QKV_STRIDE = (size_t)MR * DM;

    for (int n = 0; n < NL; n++) {
        const float* xin = (n == 0) ? x : xc_p;

        gemm_mma<<<dim3(DM/GBN, MR/GBM, 3), 256, SMEM_GEMM>>>(
            xin, pqkh + (size_t)n*3*DM*(DM/2), pqkl + (size_t)n*3*DM*(DM/2),
            nullptr, nullptr, qkv_p, MR, DM, DM, 0);

        pack_kv<<<dim3(SEQ/32, NB*NH, 2), dim3(32, 8)>>>(
            qkv_p + QKV_STRIDE, qkv_p + 2*QKV_STRIDE);

        attn_mma<<<dim3(SEQ/128, NB*NH), 128>>>(qkv_p, mask, o_p);

        gemm_mma<<<dim3(DM/GBN, MR/GBM, 1), 256, SMEM_GEMM>>>(
            o_p, pwoh + (size_t)n*DM*(DM/2), pwol + (size_t)n*DM*(DM/2),
            nullptr, xin, xc_p, MR, DM, DM, 1);

        gemm_mma<<<dim3(DF/GBN, MR/GBM, 1), 256, SMEM_GEMM>>>(
            xc_p, pw1h + (size_t)n*DF*(DM/2), pw1l + (size_t)n*DF*(DM/2),
            b1 + (size_t)n*DF, nullptr, ff_p, MR, DF, DM, 2);

        float* dst = (n == NL - 1) ? out : xc_p;
        gemm_mma<<<dim3(DM/GBN, MR/GBM, 1), 256, SMEM_GEMM>>>(
            ff_p, pw2h + (size_t)n*DM*(DF/2), pw2l + (size_t)n*DM*(DF/2),
            b2 + (size_t)n*DM, xc_p, dst, MR, DM, DF, 3);
    }
}

// round 12
// speedup vs baseline: 1.1591x; 1.0492x over previous
#include <cuda_runtime.h>
#include <math.h>
#include <stdint.h>

#define NL   4
#define NB   4
#define SEQ  2048
#define DM   256
#define NH   8
#define DH   32
#define DF   512
#define MR   (NB*SEQ)

#define NEGF (-3.402823466e38f)
#define L2E  1.44269504088896340736f
#define KSPLIT 4
#define KEYS_PER_CHUNK (SEQ/KSPLIT)   // 512

typedef unsigned long long u64;

// ================= bf16 helpers =================
__device__ __forceinline__ uint32_t pack_bf16x2(float lo, float hi) {
    uint32_t r; asm("cvt.rn.bf16x2.f32 %0, %1, %2;" : "=r"(r) : "f"(hi), "f"(lo)); return r;
}
__device__ __forceinline__ float bf_low(uint32_t p)  { return __uint_as_float(p << 16); }
__device__ __forceinline__ float bf_high(uint32_t p) { return __uint_as_float(p & 0xffff0000u); }
__device__ __forceinline__ float ex2f(float x) {
    float r; asm("ex2.approx.f32 %0, %1;" : "=f"(r) : "f"(x)); return r;
}

__device__ __forceinline__ void mma_bf16(float* c, const uint32_t* a, const uint32_t* b) {
    asm volatile(
        "mma.sync.aligned.m16n8k16.row.col.f32.bf16.bf16.f32 "
        "{%0,%1,%2,%3},{%4,%5,%6,%7},{%8,%9},{%0,%1,%2,%3};"
        : "+f"(c[0]), "+f"(c[1]), "+f"(c[2]), "+f"(c[3])
        : "r"(a[0]), "r"(a[1]), "r"(a[2]), "r"(a[3]), "r"(b[0]), "r"(b[1]));
}

// ================= scratch =================
__device__ float g_qkv [3*(size_t)MR*DM];
__device__ float g_obuf[(size_t)MR*DM];
__device__ float g_xc  [(size_t)MR*DM];
__device__ float g_ff  [(size_t)MR*DF];

// split-K attention partials (each element written by exactly one CTA)
__device__ float g_opart[KSPLIT*(size_t)MR*DM];
__device__ float g_lpart[KSPLIT*(size_t)MR*NH];

// packed K: [bh][dim-pair 16][key 2048] hi/lo;  packed V: [bh][dim 32][key-pair 1024] hi/lo
__device__ uint32_t g_kph[NB*NH*16*SEQ];
__device__ uint32_t g_kpl[NB*NH*16*SEQ];
__device__ uint32_t g_vph[NB*NH*32*(SEQ/2)];
__device__ uint32_t g_vpl[NB*NH*32*(SEQ/2)];
__device__ unsigned g_kmax2[NB*NH];        // max ||k||^2 per (b,h), float bits

// packed bf16 hi/lo weights
__device__ uint32_t g_pwqkv_h[NL*3*DM*(DM/2)];
__device__ uint32_t g_pwqkv_l[NL*3*DM*(DM/2)];
__device__ uint32_t g_pwo_h  [NL*DM*(DM/2)];
__device__ uint32_t g_pwo_l  [NL*DM*(DM/2)];
__device__ uint32_t g_pw1_h  [NL*DF*(DM/2)];
__device__ uint32_t g_pw1_l  [NL*DF*(DM/2)];
__device__ uint32_t g_pw2_h  [NL*DM*(DF/2)];
__device__ uint32_t g_pw2_l  [NL*DM*(DF/2)];

// ================= weight packing =================
__global__ void pack_qkv(const float* __restrict__ Wq,
                         const float* __restrict__ Wk,
                         const float* __restrict__ Wv) {
    int i = blockIdx.x * blockDim.x + threadIdx.x;
    const int PER_M = DM * (DM/2);
    const int TOT = NL * 3 * PER_M;
    if (i >= TOT) return;
    int l  = i / (3*PER_M);
    int r  = i % (3*PER_M);
    int m  = r / PER_M;
    int r2 = r % PER_M;
    int n  = r2 >> 7;
    int kp = r2 & 127;
    int h = n >> 5, e = n & 31;
    const float* W = (m == 0) ? Wq : (m == 1) ? Wk : Wv;
    size_t s0 = (((size_t)l*NH + h)*DM + 2*kp)*DH + e;
    float v0 = W[s0], v1 = W[s0 + DH];
    uint32_t hp = pack_bf16x2(v0, v1);
    g_pwqkv_h[i] = hp;
    g_pwqkv_l[i] = pack_bf16x2(v0 - bf_low(hp), v1 - bf_high(hp));
}

__global__ void pack_w(const float* __restrict__ W, uint32_t* __restrict__ dh,
                       uint32_t* __restrict__ dl, int K, int N) {
    int i = blockIdx.x * blockDim.x + threadIdx.x;
    int per = N * (K >> 1);
    if (i >= NL * per) return;
    int l = i / per, r = i % per;
    int n = r / (K >> 1), kp = r % (K >> 1);
    size_t s = (size_t)l*K*N + (size_t)(2*kp)*N + n;
    float v0 = W[s], v1 = W[s + N];
    uint32_t hp = pack_bf16x2(v0, v1);
    dh[i] = hp;
    dl[i] = pack_bf16x2(v0 - bf_low(hp), v1 - bf_high(hp));
}

// ================= K/V transpose + split-bf16 pack (+ K norm max) ==========
__global__ void pack_kv(const float* __restrict__ k, const float* __restrict__ v) {
    __shared__ float tl[32][33];
    int bh = blockIdx.y;
    int b = bh >> 3, h = bh & 7;
    int l0 = blockIdx.x * 32;
    const float* src = (blockIdx.z == 0) ? k : v;
    #pragma unroll
    for (int kk = 0; kk < 4; kk++) {
        int l = l0 + threadIdx.y + kk*8;
        tl[threadIdx.y + kk*8][threadIdx.x] = src[((size_t)b*SEQ + l)*DM + h*32 + threadIdx.x];
    }
    __syncthreads();
    if (blockIdx.z == 0) {
        #pragma unroll
        for (int kk = 0; kk < 2; kk++) {
            int dp = threadIdx.y + kk*8;
            float v0 = tl[threadIdx.x][2*dp], v1 = tl[threadIdx.x][2*dp+1];
            uint32_t hp = pack_bf16x2(v0, v1);
            size_t o = ((size_t)bh*16 + dp)*SEQ + l0 + threadIdx.x;
            g_kph[o] = hp;
            g_kpl[o] = pack_bf16x2(v0 - bf_low(hp), v1 - bf_high(hp));
        }
        if (threadIdx.y == 0) {
            float n2 = 0.f;
            #pragma unroll
            for (int e = 0; e < 32; e++) n2 = fmaf(tl[threadIdx.x][e], tl[threadIdx.x][e], n2);
            #pragma unroll
            for (int d = 16; d > 0; d >>= 1)
                n2 = fmaxf(n2, __shfl_xor_sync(0xffffffffu, n2, d));
            if (threadIdx.x == 0)
                atomicMax(&g_kmax2[bh], __float_as_uint(n2));
        }
    } else {
        #pragma unroll
        for (int kk = 0; kk < 2; kk++) {
            int idx = threadIdx.y*32 + threadIdx.x + kk*256;
            int e = idx >> 4, lp = idx & 15;
            float v0 = tl[2*lp][e], v1 = tl[2*lp+1][e];
            uint32_t hp = pack_bf16x2(v0, v1);
            size_t o = ((size_t)bh*32 + e)*(SEQ/2) + (l0 >> 1) + lp;
            g_vph[o] = hp;
            g_vpl[o] = pack_bf16x2(v0 - bf_low(hp), v1 - bf_high(hp));
        }
    }
}

// ================= HMMA GEMM (bf16 3-term, double-buffered) =================
#define GBM 128
#define GBN 64
#define GBK 32
#define AKP (GBK/2)
#define APAD 20

__device__ __forceinline__ float gelu_exact(float x) {
    return 0.5f * x * (1.0f + erff(x * 0.70710678118654752440f));
}

__device__ __forceinline__ void epi2(float* C, size_t off, float c0, float c1,
                                     float2 bb, const float* res, int mode) {
    float2 o;
    if (mode == 1) {
        float2 r = *(const float2*)(res + off);
        o.x = (c0 + r.x)*0.5f; o.y = (c1 + r.y)*0.5f;
    } else if (mode == 2) {
        o.x = gelu_exact(c0 + bb.x); o.y = gelu_exact(c1 + bb.y);
    } else if (mode == 3) {
        float2 r = *(const float2*)(res + off);
        o.x = (c0 + bb.x + r.x)*0.5f; o.y = (c1 + bb.y + r.y)*0.5f;
    } else {
        o.x = c0; o.y = c1;
    }
    *(float2*)(C + off) = o;
}

extern __shared__ uint32_t dsm[];

__global__ __launch_bounds__(256, 2)
void gemm_mma(const float* __restrict__ A, const uint32_t* __restrict__ Bh,
              const uint32_t* __restrict__ Bl, const float* __restrict__ bias,
              const float* __restrict__ res, float* __restrict__ C,
              int M, int N, int K, int mode) {
    uint32_t* Ash = dsm;
    uint32_t* Bsh = dsm + 2*2*GBM*APAD;

    if (mode == 0) {
        int z = blockIdx.z;
        Bh += (size_t)z * DM * (DM/2);
        Bl += (size_t)z * DM * (DM/2);
        C  += (size_t)z * (size_t)M * N;
        if (blockIdx.x == 0 && blockIdx.y == 0 && z == 0 && threadIdx.x < NB*NH)
            g_kmax2[threadIdx.x] = 0u;
    }
    int bm = blockIdx.y * GBM;
    int bn = blockIdx.x * GBN;
    int tid = threadIdx.x;
    int warp = tid >> 5, lane = tid & 31;
    int g = lane >> 2, j = lane & 3;
    int wm = (warp & 3) * 32;
    int wn = (warp >> 2) * 32;
    int ldkp = K >> 1;

    int arow = tid >> 3;
    int akp0 = (tid & 7) * 2;
    int bn0  = tid >> 2;
    int bkp0 = (tid & 3) * 4;

    const float* ap[4];
    #pragma unroll
    for (int s = 0; s < 4; s++)
        ap[s] = A + (size_t)(bm + arow + 32*s)*K + (tid & 7)*4;
    const uint32_t* bph = Bh + (size_t)(bn + bn0)*ldkp + bkp0;
    const uint32_t* bpl = Bl + (size_t)(bn + bn0)*ldkp + bkp0;

    float acc[2][4][4];
    #pragma unroll
    for (int mt = 0; mt < 2; mt++)
        #pragma unroll
        for (int n = 0; n < 4; n++)
            #pragma unroll
            for (int r = 0; r < 4; r++) acc[mt][n][r] = 0.f;

    int nt = K / GBK;
    float4 af[4]; uint4 bfh, bfl;
    #pragma unroll
    for (int s = 0; s < 4; s++) af[s] = *(const float4*)ap[s];
    bfh = *(const uint4*)bph;
    bfl = *(const uint4*)bpl;

    {
        #pragma unroll
        for (int s = 0; s < 4; s++) {
            float4 v = af[s];
            uint32_t h0 = pack_bf16x2(v.x, v.y);
            uint32_t h1 = pack_bf16x2(v.z, v.w);
            uint32_t l0 = pack_bf16x2(v.x - bf_low(h0), v.y - bf_high(h0));
            uint32_t l1 = pack_bf16x2(v.z - bf_low(h1), v.w - bf_high(h1));
            int row = arow + 32*s;
            uint32_t* ph = Ash + row*APAD + akp0;
            uint32_t* pl = Ash + GBM*APAD + row*APAD + akp0;
            ph[0] = h0; ph[1] = h1; pl[0] = l0; pl[1] = l1;
        }
        uint32_t* ph = Bsh + bn0*APAD + bkp0;
        uint32_t* pl = Bsh + GBN*APAD + bn0*APAD + bkp0;
        ph[0]=bfh.x; ph[1]=bfh.y; ph[2]=bfh.z; ph[3]=bfh.w;
        pl[0]=bfl.x; pl[1]=bfl.y; pl[2]=bfl.z; pl[3]=bfl.w;
    }
    __syncthreads();

    for (int t = 0; t < nt; t++) {
        int buf = t & 1;
        if (t + 1 < nt) {
            int k0 = (t+1)*GBK;
            #pragma unroll
            for (int s = 0; s < 4; s++) af[s] = *(const float4*)(ap[s] + k0);
            bfh = *(const uint4*)(bph + (t+1)*AKP);
            bfl = *(const uint4*)(bpl + (t+1)*AKP);
        }

        const uint32_t* Ab = Ash + buf*2*GBM*APAD;
        const uint32_t* Bb = Bsh + buf*2*GBN*APAD;
        #pragma unroll
        for (int kc = 0; kc < 2; kc++) {
            uint32_t ah[2][4], al[2][4];
            #pragma unroll
            for (int mt = 0; mt < 2; mt++) {
                int r0 = wm + mt*16 + g;
                const uint32_t* pa  = Ab;
                const uint32_t* pal = Ab + GBM*APAD;
                ah[mt][0] = pa [(r0)  *APAD + kc*8 + j];
                ah[mt][1] = pa [(r0+8)*APAD + kc*8 + j];
                ah[mt][2] = pa [(r0)  *APAD + kc*8 + j + 4];
                ah[mt][3] = pa [(r0+8)*APAD + kc*8 + j + 4];
                al[mt][0] = pal[(r0)  *APAD + kc*8 + j];
                al[mt][1] = pal[(r0+8)*APAD + kc*8 + j];
                al[mt][2] = pal[(r0)  *APAD + kc*8 + j + 4];
                al[mt][3] = pal[(r0+8)*APAD + kc*8 + j + 4];
            }
            #pragma unroll
            for (int n = 0; n < 4; n++) {
                int c0 = wn + n*8 + g;
                uint32_t bh2[2], bl2[2];
                bh2[0] = Bb[c0*APAD + kc*8 + j];
                bh2[1] = Bb[c0*APAD + kc*8 + j + 4];
                bl2[0] = Bb[GBN*APAD + c0*APAD + kc*8 + j];
                bl2[1] = Bb[GBN*APAD + c0*APAD + kc*8 + j + 4];
                #pragma unroll
                for (int mt = 0; mt < 2; mt++) {
                    mma_bf16(acc[mt][n], ah[mt], bh2);
                    mma_bf16(acc[mt][n], al[mt], bh2);
                    mma_bf16(acc[mt][n], ah[mt], bl2);
                }
            }
        }

        if (t + 1 < nt) {
            int nb = buf ^ 1;
            uint32_t* An = Ash + nb*2*GBM*APAD;
            uint32_t* Bn = Bsh + nb*2*GBN*APAD;
            #pragma unroll
            for (int s = 0; s < 4; s++) {
                float4 v = af[s];
                uint32_t h0 = pack_bf16x2(v.x, v.y);
                uint32_t h1 = pack_bf16x2(v.z, v.w);
                uint32_t l0 = pack_bf16x2(v.x - bf_low(h0), v.y - bf_high(h0));
                uint32_t l1 = pack_bf16x2(v.z - bf_low(h1), v.w - bf_high(h1));
                int row = arow + 32*s;
                uint32_t* ph = An + row*APAD + akp0;
                uint32_t* pl = An + GBM*APAD + row*APAD + akp0;
                ph[0] = h0; ph[1] = h1; pl[0] = l0; pl[1] = l1;
            }
            uint32_t* ph = Bn + bn0*APAD + bkp0;
            uint32_t* pl = Bn + GBN*APAD + bn0*APAD + bkp0;
            ph[0]=bfh.x; ph[1]=bfh.y; ph[2]=bfh.z; ph[3]=bfh.w;
            pl[0]=bfl.x; pl[1]=bfl.y; pl[2]=bfl.z; pl[3]=bfl.w;
        }
        __syncthreads();
    }

    float2 bb[4];
    #pragma unroll
    for (int n = 0; n < 4; n++) {
        if (mode == 2 || mode == 3)
            bb[n] = *(const float2*)(bias + bn + wn + n*8 + 2*j);
        else
            bb[n] = make_float2(0.f, 0.f);
    }
    #pragma unroll
    for (int mt = 0; mt < 2; mt++) {
        int r0 = bm + wm + mt*16 + g;
        #pragma unroll
        for (int n = 0; n < 4; n++) {
            int col = bn + wn + n*8 + 2*j;
            size_t o0 = (size_t)r0*N + col;
            size_t o1 = (size_t)(r0 + 8)*N + col;
            epi2(C, o0, acc[mt][n][0], acc[mt][n][1], bb[n], res, mode);
            epi2(C, o1, acc[mt][n][2], acc[mt][n][3], bb[n], res, mode);
        }
    }
}

// ================= warp-MMA flash attention (split-K, static bound, exp2) ===
#define KT  32
#define NITC (KEYS_PER_CHUNK/KT)   // 16 iterations per chunk

__global__ __launch_bounds__(128, 3)
void attn_mma(const float* __restrict__ gq, const float* __restrict__ gmask) {
    __shared__ __align__(16) uint32_t Ksh[2][2][16][40];
    __shared__ __align__(16) uint32_t Vsh[2][2][32][20];
    __shared__ float sMask[2][KT];   // stores (1-mk)*NEGF

    int tid  = threadIdx.x;
    int warp = tid >> 5;
    int lane = tid & 31;
    int g    = lane >> 2;
    int j    = lane & 3;
    int bh   = blockIdx.y;
    int b    = bh >> 3, h = bh & 7;
    int q0   = blockIdx.x * 128 + warp * 32;
    int z    = blockIdx.z;

    // Q fragments, pre-scaled by log2(e) so softmax runs in ex2 domain
    uint32_t qh[2][2][4], ql[2][2][4];
    float qn2[2][2] = {};
    #pragma unroll
    for (int mt = 0; mt < 2; mt++) {
        #pragma unroll
        for (int rr = 0; rr < 2; rr++) {
            int row = q0 + mt*16 + g + rr*8;
            const float* qp = gq + ((size_t)b*SEQ + row)*DM + h*DH;
            #pragma unroll
            for (int u = 0; u < 4; u++) {
                float2 v = *(const float2*)(qp + u*8 + 2*j);
                v.x *= L2E; v.y *= L2E;
                qn2[mt][rr] = fmaf(v.x, v.x, fmaf(v.y, v.y, qn2[mt][rr]));
                uint32_t hp = pack_bf16x2(v.x, v.y);
                uint32_t lp = pack_bf16x2(v.x - bf_low(hp), v.y - bf_high(hp));
                qh[mt][u>>1][rr + 2*(u&1)] = hp;
                ql[mt][u>>1][rr + 2*(u&1)] = lp;
            }
        }
    }
    #pragma unroll
    for (int mt = 0; mt < 2; mt++)
        #pragma unroll
        for (int rr = 0; rr < 2; rr++) {
            qn2[mt][rr] += __shfl_xor_sync(0xffffffffu, qn2[mt][rr], 1);
            qn2[mt][rr] += __shfl_xor_sync(0xffffffffu, qn2[mt][rr], 2);
        }

    // |q*L2E| * |k| bounds s*log2e; 43.28 = 30*log2e slack
    float kmaxn = sqrtf(__uint_as_float(g_kmax2[bh]));
    float fm[2][2], cb[2][2];
    #pragma unroll
    for (int mt = 0; mt < 2; mt++) {
        fm[mt][0] = gmask[b*SEQ + q0 + mt*16 + g];
        fm[mt][1] = gmask[b*SEQ + q0 + mt*16 + g + 8];
        #pragma unroll
        for (int rr = 0; rr < 2; rr++)
            cb[mt][rr] = (fm[mt][rr] == 0.f) ? 0.f
                       : -(sqrtf(qn2[mt][rr]) * kmaxn - 43.2808512266689f);
    }

    float lrow[2][2], ofr[2][4][4];
    #pragma unroll
    for (int mt = 0; mt < 2; mt++) {
        lrow[mt][0] = 0.f; lrow[mt][1] = 0.f;
        #pragma unroll
        for (int nd = 0; nd < 4; nd++)
            #pragma unroll
            for (int r = 0; r < 4; r++) ofr[mt][nd][r] = 0.f;
    }

    int kdp = tid >> 3;
    int kkg = (tid & 7) * 4;
    int vdm = tid >> 2;
    int vpg = (tid & 3) * 4;
    const uint32_t* kbh = g_kph + ((size_t)bh*16 + kdp)*SEQ + z*KEYS_PER_CHUNK + kkg;
    const uint32_t* kbl = g_kpl + ((size_t)bh*16 + kdp)*SEQ + z*KEYS_PER_CHUNK + kkg;
    const uint32_t* vbh = g_vph + ((size_t)bh*32 + vdm)*(SEQ/2) + z*(KEYS_PER_CHUNK/2) + vpg;
    const uint32_t* vbl = g_vpl + ((size_t)bh*32 + vdm)*(SEQ/2) + z*(KEYS_PER_CHUNK/2) + vpg;
    const float* mbase = gmask + b*SEQ + z*KEYS_PER_CHUNK + tid;

    uint4 rkh, rkl, rvh, rvl; float ml = 0.f;
    rkh = *(const uint4*)(kbh);
    rkl = *(const uint4*)(kbl);
    rvh = *(const uint4*)(vbh);
    rvl = *(const uint4*)(vbl);
    if (tid < KT) ml = *mbase;

    *(uint4*)&Ksh[0][0][kdp][kkg] = rkh;
    *(uint4*)&Ksh[0][1][kdp][kkg] = rkl;
    *(uint4*)&Vsh[0][0][vdm][vpg] = rvh;
    *(uint4*)&Vsh[0][1][vdm][vpg] = rvl;
    if (tid < KT) sMask[0][tid] = (1.0f - ml) * NEGF;
    __syncthreads();

    for (int it = 0; it < NITC; it++) {
        int bufc = it & 1;
        if (it + 1 < NITC) {
            rkh = *(const uint4*)(kbh + (it+1)*KT);
            rkl = *(const uint4*)(kbl + (it+1)*KT);
            rvh = *(const uint4*)(vbh + (it+1)*(KT/2));
            rvl = *(const uint4*)(vbl + (it+1)*(KT/2));
            if (tid < KT) ml = mbase[(it+1)*KT];
        }

        float sfr[2][4][4];
        #pragma unroll
        for (int mt = 0; mt < 2; mt++)
            #pragma unroll
            for (int n = 0; n < 4; n++)
                #pragma unroll
                for (int r = 0; r < 4; r++) sfr[mt][n][r] = 0.f;

        #pragma unroll
        for (int n = 0; n < 4; n++) {
            #pragma unroll
            for (int ks = 0; ks < 2; ks++) {
                uint32_t bhi[2], blo[2];
                bhi[0] = Ksh[bufc][0][ks*8 + j][n*8 + g];
                bhi[1] = Ksh[bufc][0][ks*8 + j + 4][n*8 + g];
                blo[0] = Ksh[bufc][1][ks*8 + j][n*8 + g];
                blo[1] = Ksh[bufc][1][ks*8 + j + 4][n*8 + g];
                #pragma unroll
                for (int mt = 0; mt < 2; mt++) {
                    mma_bf16(sfr[mt][n], qh[mt][ks], bhi);
                    mma_bf16(sfr[mt][n], ql[mt][ks], bhi);
                    mma_bf16(sfr[mt][n], qh[mt][ks], blo);
                }
            }
        }

        // ---- softmax, exp2 domain: p = ex2(fm*(s2 + mk) + cb) ----
        uint32_t phr0[2][4], phr1[2][4], plr0[2][4], plr1[2][4];
        #pragma unroll
        for (int mt = 0; mt < 2; mt++) {
            float f0 = fm[mt][0], f1 = fm[mt][1];
            float c0 = cb[mt][0], c1 = cb[mt][1];
            float ls0 = 0.f, ls1 = 0.f;
            #pragma unroll
            for (int n = 0; n < 4; n++) {
                float mk0 = sMask[bufc][n*8 + 2*j];
                float mk1 = sMask[bufc][n*8 + 2*j + 1];
                float p0 = ex2f(fmaf(f0, sfr[mt][n][0] + mk0, c0));
                float p1 = ex2f(fmaf(f0, sfr[mt][n][1] + mk1, c0));
                float p2 = ex2f(fmaf(f1, sfr[mt][n][2] + mk0, c1));
                float p3 = ex2f(fmaf(f1, sfr[mt][n][3] + mk1, c1));
                ls0 += p0 + p1; ls1 += p2 + p3;
                uint32_t h01 = pack_bf16x2(p0, p1);
                uint32_t h23 = pack_bf16x2(p2, p3);
                phr0[mt][n] = h01;
                phr1[mt][n] = h23;
                plr0[mt][n] = pack_bf16x2(p0 - bf_low(h01), p1 - bf_high(h01));
                plr1[mt][n] = pack_bf16x2(p2 - bf_low(h23), p3 - bf_high(h23));
            }
            lrow[mt][0] += ls0; lrow[mt][1] += ls1;
        }

        #pragma unroll
        for (int nd = 0; nd < 4; nd++) {
            #pragma unroll
            for (int k2 = 0; k2 < 2; k2++) {
                uint32_t bhi[2], blo[2];
                bhi[0] = Vsh[bufc][0][nd*8 + g][k2*8 + j];
                bhi[1] = Vsh[bufc][0][nd*8 + g][k2*8 + j + 4];
                blo[0] = Vsh[bufc][1][nd*8 + g][k2*8 + j];
                blo[1] = Vsh[bufc][1][nd*8 + g][k2*8 + j + 4];
                #pragma unroll
                for (int mt = 0; mt < 2; mt++) {
                    uint32_t ahi[4] = {phr0[mt][2*k2], phr1[mt][2*k2],
                                       phr0[mt][2*k2+1], phr1[mt][2*k2+1]};
                    uint32_t alo[4] = {plr0[mt][2*k2], plr1[mt][2*k2],
                                       plr0[mt][2*k2+1], plr1[mt][2*k2+1]};
                    mma_bf16(ofr[mt][nd], ahi, bhi);
                    mma_bf16(ofr[mt][nd], ahi, blo);
                    mma_bf16(ofr[mt][nd], alo, bhi);
                }
            }
        }

        if (it + 1 < NITC) {
            int bufn = bufc ^ 1;
            *(uint4*)&Ksh[bufn][0][kdp][kkg] = rkh;
            *(uint4*)&Ksh[bufn][1][kdp][kkg] = rkl;
            *(uint4*)&Vsh[bufn][0][vdm][vpg] = rvh;
            *(uint4*)&Vsh[bufn][1][vdm][vpg] = rvl;
            if (tid < KT) sMask[bufn][tid] = (1.0f - ml) * NEGF;
        }
        __syncthreads();
    }

    // ---- epilogue: write RAW partial sums to plane z (exact-once writes) ----
    float* opart = g_opart + (size_t)z * MR * DM;
    #pragma unroll
    for (int mt = 0; mt < 2; mt++) {
        float l0 = lrow[mt][0], l1 = lrow[mt][1];
        l0 += __shfl_xor_sync(0xffffffffu, l0, 1);
        l0 += __shfl_xor_sync(0xffffffffu, l0, 2);
        l1 += __shfl_xor_sync(0xffffffffu, l1, 1);
        l1 += __shfl_xor_sync(0xffffffffu, l1, 2);
        int r0 = q0 + mt*16 + g;
        if (j == 0) {
            g_lpart[((size_t)z*MR + b*SEQ + r0)*NH + h]     = l0;
            g_lpart[((size_t)z*MR + b*SEQ + r0 + 8)*NH + h] = l1;
        }
        #pragma unroll
        for (int nd = 0; nd < 4; nd++) {
            int col = h*DH + nd*8 + 2*j;
            float2 v0 = make_float2(ofr[mt][nd][0], ofr[mt][nd][1]);
            float2 v1 = make_float2(ofr[mt][nd][2], ofr[mt][nd][3]);
            *(float2*)(opart + ((size_t)b*SEQ + r0)*DM + col)     = v0;
            *(float2*)(opart + ((size_t)b*SEQ + r0 + 8)*DM + col) = v1;
        }
    }
}

// ================= combine split-K partials: o = (sum_z O_z) / (sum_z l_z) ==
__global__ void combine_o(float* __restrict__ go) {
    size_t base = ((size_t)blockIdx.x * 256 + threadIdx.x) * 4;
    if (base >= (size_t)MR * DM) return;
    size_t brow = base / DM;
    int col = (int)(base % DM);
    int h = col >> 5;
    float l = 0.f;
    #pragma unroll
    for (int z = 0; z < KSPLIT; z++)
        l += g_lpart[((size_t)z*MR + brow)*NH + h];
    float4 o = make_float4(0.f, 0.f, 0.f, 0.f);
    #pragma unroll
    for (int z = 0; z < KSPLIT; z++) {
        float4 t = *(const float4*)&g_opart[(size_t)z*MR*DM + base];
        o.x += t.x; o.y += t.y; o.z += t.z; o.w += t.w;
    }
    float inv = 1.0f / l;
    o.x *= inv; o.y *= inv; o.z *= inv; o.w *= inv;
    *(float4*)&go[base] = o;
}

// ================= launch =================
extern "C" void kernel_launch(void* const* d_in, const int* in_sizes, int n_in,
                              void* d_out, int out_size) {
    const float* x    = (const float*)d_in[0];
    const float* mask = (const float*)d_in[1];
    const float* Wq   = (const float*)d_in[2];
    const float* Wk   = (const float*)d_in[3];
    const float* Wv   = (const float*)d_in[4];
    const float* Wo   = (const float*)d_in[5];
    const float* W1   = (const float*)d_in[6];
    const float* b1   = (const float*)d_in[7];
    const float* W2   = (const float*)d_in[8];
    const float* b2   = (const float*)d_in[9];
    float* out = (float*)d_out;

    float *qkv_p, *o_p, *xc_p, *ff_p;
    uint32_t *pqkh, *pqkl, *pwoh, *pwol, *pw1h, *pw1l, *pw2h, *pw2l;
    cudaGetSymbolAddress((void**)&qkv_p, g_qkv);
    cudaGetSymbolAddress((void**)&o_p,   g_obuf);
    cudaGetSymbolAddress((void**)&xc_p,  g_xc);
    cudaGetSymbolAddress((void**)&ff_p,  g_ff);
    cudaGetSymbolAddress((void**)&pqkh,  g_pwqkv_h);
    cudaGetSymbolAddress((void**)&pqkl,  g_pwqkv_l);
    cudaGetSymbolAddress((void**)&pwoh,  g_pwo_h);
    cudaGetSymbolAddress((void**)&pwol,  g_pwo_l);
    cudaGetSymbolAddress((void**)&pw1h,  g_pw1_h);
    cudaGetSymbolAddress((void**)&pw1l,  g_pw1_l);
    cudaGetSymbolAddress((void**)&pw2h,  g_pw2_h);
    cudaGetSymbolAddress((void**)&pw2l,  g_pw2_l);

    const int SMEM_GEMM = (2*2*GBM*APAD + 2*2*GBN*APAD) * 4;
    cudaFuncSetAttribute(gemm_mma, cudaFuncAttributeMaxDynamicSharedMemorySize, SMEM_GEMM);

    pack_qkv<<<(NL*3*DM*(DM/2) + 255)/256, 256>>>(Wq, Wk, Wv);
    pack_w<<<(NL*DM*(DM/2) + 255)/256, 256>>>(Wo, pwoh, pwol, DM, DM);
    pack_w<<<(NL*DF*(DM/2) + 255)/256, 256>>>(W1, pw1h, pw1l, DM, DF);
    pack_w<<<(NL*DM*(DF/2) + 255)/256, 256>>>(W2, pw2h, pw2l, DF, DM);

    const size_t QKV_STRIDE = (size_t)MR * DM;

    for (int n = 0; n < NL; n++) {
        const float* xin = (n == 0) ? x : xc_p;

        gemm_mma<<<dim3(DM/GBN, MR/GBM, 3), 256, SMEM_GEMM>>>(
            xin, pqkh + (size_t)n*3*DM*(DM/2), pqkl + (size_t)n*3*DM*(DM/2),
            nullptr, nullptr, qkv_p, MR, DM, DM, 0);

        pack_kv<<<dim3(SEQ/32, NB*NH, 2), dim3(32, 8)>>>(
            qkv_p + QKV_STRIDE, qkv_p + 2*QKV_STRIDE);

        attn_mma<<<dim3(SEQ/128, NB*NH, KSPLIT), 128>>>(qkv_p, mask);

        combine_o<<<(MR*DM/4 + 255)/256, 256>>>(o_p);

        gemm_mma<<<dim3(DM/GBN, MR/GBM, 1), 256, SMEM_GEMM>>>(
            o_p, pwoh + (size_t)n*DM*(DM/2), pwol + (size_t)n*DM*(DM/2),
            nullptr, xin, xc_p, MR, DM, DM, 1);

        gemm_mma<<<dim3(DF/GBN, MR/GBM, 1), 256, SMEM_GEMM>>>(
            xc_p, pw1h + (size_t)n*DF*(DM/2), pw1l + (size_t)n*DF*(DM/2),
            b1 + (size_t)n*DF, nullptr, ff_p, MR, DF, DM, 2);

        float* dst = (n == NL - 1) ? out : xc_p;
        gemm_mma<<<dim3(DM/GBN, MR/GBM, 1), 256, SMEM_GEMM>>>(
            ff_p, pw2h + (size_t)n*DM*(DF/2), pw2l + (size_t)n*DM*(DF/2),
            b2 + (size_t)n*DM, xc_p, dst, MR, DM, DF, 3);
    }
}

// round 13
// speedup vs baseline: 1.1659x; 1.0058x over previous
#include <cuda_runtime.h>
#include <math.h>
#include <stdint.h>

#define NL   4
#define NB   4
#define SEQ  2048
#define DM   256
#define NH   8
#define DH   32
#define DF   512
#define MR   (NB*SEQ)

#define NEGF (-3.402823466e38f)
#define L2E  1.44269504088896340736f
#define KSPLIT 4
#define KEYS_PER_CHUNK (SEQ/KSPLIT)   // 512

typedef unsigned long long u64;

// ================= bf16 helpers =================
__device__ __forceinline__ uint32_t pack_bf16x2(float lo, float hi) {
    uint32_t r; asm("cvt.rn.bf16x2.f32 %0, %1, %2;" : "=r"(r) : "f"(hi), "f"(lo)); return r;
}
__device__ __forceinline__ float bf_low(uint32_t p)  { return __uint_as_float(p << 16); }
__device__ __forceinline__ float bf_high(uint32_t p) { return __uint_as_float(p & 0xffff0000u); }
__device__ __forceinline__ float ex2f(float x) {
    float r; asm("ex2.approx.f32 %0, %1;" : "=f"(r) : "f"(x)); return r;
}

__device__ __forceinline__ void mma_bf16(float* c, const uint32_t* a, const uint32_t* b) {
    asm volatile(
        "mma.sync.aligned.m16n8k16.row.col.f32.bf16.bf16.f32 "
        "{%0,%1,%2,%3},{%4,%5,%6,%7},{%8,%9},{%0,%1,%2,%3};"
        : "+f"(c[0]), "+f"(c[1]), "+f"(c[2]), "+f"(c[3])
        : "r"(a[0]), "r"(a[1]), "r"(a[2]), "r"(a[3]), "r"(b[0]), "r"(b[1]));
}

// ================= scratch =================
__device__ float g_qkv [3*(size_t)MR*DM];
__device__ float g_obuf[(size_t)MR*DM];
__device__ float g_xc  [(size_t)MR*DM];
__device__ float g_ff  [(size_t)MR*DF];

// split-K attention partials (each element written by exactly one CTA)
__device__ float g_opart[KSPLIT*(size_t)MR*DM];
__device__ float g_lpart[KSPLIT*(size_t)MR*NH];

// packed K: [bh][dim-pair 16][key 2048] hi/lo;  packed V: [bh][dim 32][key-pair 1024] hi/lo
__device__ uint32_t g_kph[NB*NH*16*SEQ];
__device__ uint32_t g_kpl[NB*NH*16*SEQ];
__device__ uint32_t g_vph[NB*NH*32*(SEQ/2)];
__device__ uint32_t g_vpl[NB*NH*32*(SEQ/2)];
// packed Q (L2E-prescaled, fragment-permuted): [bh][row][(kp&3)*4 + (kp>>2)]
__device__ uint32_t g_qph[(size_t)NB*NH*SEQ*16];
__device__ uint32_t g_qpl[(size_t)NB*NH*SEQ*16];
__device__ float    g_qn [(size_t)NB*NH*SEQ];      // |q*L2E|^2 per (bh,row)
__device__ unsigned g_kmax2[NB*NH];                // max ||k||^2 per (b,h), float bits

// packed bf16 hi/lo weights
__device__ uint32_t g_pwqkv_h[NL*3*DM*(DM/2)];
__device__ uint32_t g_pwqkv_l[NL*3*DM*(DM/2)];
__device__ uint32_t g_pwo_h  [NL*DM*(DM/2)];
__device__ uint32_t g_pwo_l  [NL*DM*(DM/2)];
__device__ uint32_t g_pw1_h  [NL*DF*(DM/2)];
__device__ uint32_t g_pw1_l  [NL*DF*(DM/2)];
__device__ uint32_t g_pw2_h  [NL*DM*(DF/2)];
__device__ uint32_t g_pw2_l  [NL*DM*(DF/2)];

// ================= weight packing =================
__global__ void pack_qkv(const float* __restrict__ Wq,
                         const float* __restrict__ Wk,
                         const float* __restrict__ Wv) {
    int i = blockIdx.x * blockDim.x + threadIdx.x;
    const int PER_M = DM * (DM/2);
    const int TOT = NL * 3 * PER_M;
    if (i >= TOT) return;
    int l  = i / (3*PER_M);
    int r  = i % (3*PER_M);
    int m  = r / PER_M;
    int r2 = r % PER_M;
    int n  = r2 >> 7;
    int kp = r2 & 127;
    int h = n >> 5, e = n & 31;
    const float* W = (m == 0) ? Wq : (m == 1) ? Wk : Wv;
    size_t s0 = (((size_t)l*NH + h)*DM + 2*kp)*DH + e;
    float v0 = W[s0], v1 = W[s0 + DH];
    uint32_t hp = pack_bf16x2(v0, v1);
    g_pwqkv_h[i] = hp;
    g_pwqkv_l[i] = pack_bf16x2(v0 - bf_low(hp), v1 - bf_high(hp));
}

__global__ void pack_w(const float* __restrict__ W, uint32_t* __restrict__ dh,
                       uint32_t* __restrict__ dl, int K, int N) {
    int i = blockIdx.x * blockDim.x + threadIdx.x;
    int per = N * (K >> 1);
    if (i >= NL * per) return;
    int l = i / per, r = i % per;
    int n = r / (K >> 1), kp = r % (K >> 1);
    size_t s = (size_t)l*K*N + (size_t)(2*kp)*N + n;
    float v0 = W[s], v1 = W[s + N];
    uint32_t hp = pack_bf16x2(v0, v1);
    dh[i] = hp;
    dl[i] = pack_bf16x2(v0 - bf_low(hp), v1 - bf_high(hp));
}

// ================= Q/K/V transpose + split-bf16 pack ========================
// z=0: K [l][e] -> kp[bh][dp][l]; + per-(b,h) max row norm
// z=1: V [l][e] -> vp[bh][e][lp]
// z=2: Q [l][e] -> qp[bh][l][perm(kp)], scaled by L2E; + per-row |q*L2E|^2
__global__ void pack_kv(const float* __restrict__ q, const float* __restrict__ k,
                        const float* __restrict__ v) {
    __shared__ float tl[32][33];
    int bh = blockIdx.y;
    int b = bh >> 3, h = bh & 7;
    int l0 = blockIdx.x * 32;
    const float* src = (blockIdx.z == 0) ? k : (blockIdx.z == 1) ? v : q;
    #pragma unroll
    for (int kk = 0; kk < 4; kk++) {
        int l = l0 + threadIdx.y + kk*8;
        tl[threadIdx.y + kk*8][threadIdx.x] = src[((size_t)b*SEQ + l)*DM + h*32 + threadIdx.x];
    }
    __syncthreads();
    if (blockIdx.z == 0) {
        #pragma unroll
        for (int kk = 0; kk < 2; kk++) {
            int dp = threadIdx.y + kk*8;
            float v0 = tl[threadIdx.x][2*dp], v1 = tl[threadIdx.x][2*dp+1];
            uint32_t hp = pack_bf16x2(v0, v1);
            size_t o = ((size_t)bh*16 + dp)*SEQ + l0 + threadIdx.x;
            g_kph[o] = hp;
            g_kpl[o] = pack_bf16x2(v0 - bf_low(hp), v1 - bf_high(hp));
        }
        if (threadIdx.y == 0) {
            float n2 = 0.f;
            #pragma unroll
            for (int e = 0; e < 32; e++) n2 = fmaf(tl[threadIdx.x][e], tl[threadIdx.x][e], n2);
            #pragma unroll
            for (int d = 16; d > 0; d >>= 1)
                n2 = fmaxf(n2, __shfl_xor_sync(0xffffffffu, n2, d));
            if (threadIdx.x == 0)
                atomicMax(&g_kmax2[bh], __float_as_uint(n2));
        }
    } else if (blockIdx.z == 1) {
        #pragma unroll
        for (int kk = 0; kk < 2; kk++) {
            int idx = threadIdx.y*32 + threadIdx.x + kk*256;
            int e = idx >> 4, lp = idx & 15;
            float v0 = tl[2*lp][e], v1 = tl[2*lp+1][e];
            uint32_t hp = pack_bf16x2(v0, v1);
            size_t o = ((size_t)bh*32 + e)*(SEQ/2) + (l0 >> 1) + lp;
            g_vph[o] = hp;
            g_vpl[o] = pack_bf16x2(v0 - bf_low(hp), v1 - bf_high(hp));
        }
    } else {
        #pragma unroll
        for (int kk = 0; kk < 2; kk++) {
            int idx = threadIdx.y*32 + threadIdx.x + kk*256;   // 0..511
            int row = idx >> 4;       // 0..31
            int kp  = idx & 15;
            float v0 = tl[row][2*kp]   * L2E;
            float v1 = tl[row][2*kp+1] * L2E;
            uint32_t hp = pack_bf16x2(v0, v1);
            size_t o = ((size_t)bh*SEQ + l0 + row)*16 + (kp & 3)*4 + (kp >> 2);
            g_qph[o] = hp;
            g_qpl[o] = pack_bf16x2(v0 - bf_low(hp), v1 - bf_high(hp));
        }
        if (threadIdx.y == 0) {
            float n2 = 0.f;
            #pragma unroll
            for (int e = 0; e < 32; e++) {
                float vv = tl[threadIdx.x][e] * L2E;
                n2 = fmaf(vv, vv, n2);
            }
            g_qn[(size_t)bh*SEQ + l0 + threadIdx.x] = n2;
        }
    }
}

// ================= HMMA GEMM (bf16 3-term, double-buffered) =================
#define GBM 128
#define GBN 64
#define GBK 32
#define AKP (GBK/2)
#define APAD 20

__device__ __forceinline__ float gelu_exact(float x) {
    return 0.5f * x * (1.0f + erff(x * 0.70710678118654752440f));
}

__device__ __forceinline__ void epi2(float* C, size_t off, float c0, float c1,
                                     float2 bb, const float* res, int mode) {
    float2 o;
    if (mode == 1) {
        float2 r = *(const float2*)(res + off);
        o.x = (c0 + r.x)*0.5f; o.y = (c1 + r.y)*0.5f;
    } else if (mode == 2) {
        o.x = gelu_exact(c0 + bb.x); o.y = gelu_exact(c1 + bb.y);
    } else if (mode == 3) {
        float2 r = *(const float2*)(res + off);
        o.x = (c0 + bb.x + r.x)*0.5f; o.y = (c1 + bb.y + r.y)*0.5f;
    } else {
        o.x = c0; o.y = c1;
    }
    *(float2*)(C + off) = o;
}

extern __shared__ uint32_t dsm[];

__global__ __launch_bounds__(256, 2)
void gemm_mma(const float* __restrict__ A, const uint32_t* __restrict__ Bh,
              const uint32_t* __restrict__ Bl, const float* __restrict__ bias,
              const float* __restrict__ res, float* __restrict__ C,
              int M, int N, int K, int mode) {
    uint32_t* Ash = dsm;
    uint32_t* Bsh = dsm + 2*2*GBM*APAD;

    if (mode == 0) {
        int z = blockIdx.z;
        Bh += (size_t)z * DM * (DM/2);
        Bl += (size_t)z * DM * (DM/2);
        C  += (size_t)z * (size_t)M * N;
        if (blockIdx.x == 0 && blockIdx.y == 0 && z == 0 && threadIdx.x < NB*NH)
            g_kmax2[threadIdx.x] = 0u;
    }
    int bm = blockIdx.y * GBM;
    int bn = blockIdx.x * GBN;
    int tid = threadIdx.x;
    int warp = tid >> 5, lane = tid & 31;
    int g = lane >> 2, j = lane & 3;
    int wm = (warp & 3) * 32;
    int wn = (warp >> 2) * 32;
    int ldkp = K >> 1;

    int arow = tid >> 3;
    int akp0 = (tid & 7) * 2;
    int bn0  = tid >> 2;
    int bkp0 = (tid & 3) * 4;

    const float* ap[4];
    #pragma unroll
    for (int s = 0; s < 4; s++)
        ap[s] = A + (size_t)(bm + arow + 32*s)*K + (tid & 7)*4;
    const uint32_t* bph = Bh + (size_t)(bn + bn0)*ldkp + bkp0;
    const uint32_t* bpl = Bl + (size_t)(bn + bn0)*ldkp + bkp0;

    float acc[2][4][4];
    #pragma unroll
    for (int mt = 0; mt < 2; mt++)
        #pragma unroll
        for (int n = 0; n < 4; n++)
            #pragma unroll
            for (int r = 0; r < 4; r++) acc[mt][n][r] = 0.f;

    int nt = K / GBK;
    float4 af[4]; uint4 bfh, bfl;
    #pragma unroll
    for (int s = 0; s < 4; s++) af[s] = *(const float4*)ap[s];
    bfh = *(const uint4*)bph;
    bfl = *(const uint4*)bpl;

    {
        #pragma unroll
        for (int s = 0; s < 4; s++) {
            float4 v = af[s];
            uint32_t h0 = pack_bf16x2(v.x, v.y);
            uint32_t h1 = pack_bf16x2(v.z, v.w);
            uint32_t l0 = pack_bf16x2(v.x - bf_low(h0), v.y - bf_high(h0));
            uint32_t l1 = pack_bf16x2(v.z - bf_low(h1), v.w - bf_high(h1));
            int row = arow + 32*s;
            uint32_t* ph = Ash + row*APAD + akp0;
            uint32_t* pl = Ash + GBM*APAD + row*APAD + akp0;
            ph[0] = h0; ph[1] = h1; pl[0] = l0; pl[1] = l1;
        }
        uint32_t* ph = Bsh + bn0*APAD + bkp0;
        uint32_t* pl = Bsh + GBN*APAD + bn0*APAD + bkp0;
        ph[0]=bfh.x; ph[1]=bfh.y; ph[2]=bfh.z; ph[3]=bfh.w;
        pl[0]=bfl.x; pl[1]=bfl.y; pl[2]=bfl.z; pl[3]=bfl.w;
    }
    __syncthreads();

    for (int t = 0; t < nt; t++) {
        int buf = t & 1;
        if (t + 1 < nt) {
            int k0 = (t+1)*GBK;
            #pragma unroll
            for (int s = 0; s < 4; s++) af[s] = *(const float4*)(ap[s] + k0);
            bfh = *(const uint4*)(bph + (t+1)*AKP);
            bfl = *(const uint4*)(bpl + (t+1)*AKP);
        }

        const uint32_t* Ab = Ash + buf*2*GBM*APAD;
        const uint32_t* Bb = Bsh + buf*2*GBN*APAD;
        #pragma unroll
        for (int kc = 0; kc < 2; kc++) {
            uint32_t ah[2][4], al[2][4];
            #pragma unroll
            for (int mt = 0; mt < 2; mt++) {
                int r0 = wm + mt*16 + g;
                const uint32_t* pa  = Ab;
                const uint32_t* pal = Ab + GBM*APAD;
                ah[mt][0] = pa [(r0)  *APAD + kc*8 + j];
                ah[mt][1] = pa [(r0+8)*APAD + kc*8 + j];
                ah[mt][2] = pa [(r0)  *APAD + kc*8 + j + 4];
                ah[mt][3] = pa [(r0+8)*APAD + kc*8 + j + 4];
                al[mt][0] = pal[(r0)  *APAD + kc*8 + j];
                al[mt][1] = pal[(r0+8)*APAD + kc*8 + j];
                al[mt][2] = pal[(r0)  *APAD + kc*8 + j + 4];
                al[mt][3] = pal[(r0+8)*APAD + kc*8 + j + 4];
            }
            #pragma unroll
            for (int n = 0; n < 4; n++) {
                int c0 = wn + n*8 + g;
                uint32_t bh2[2], bl2[2];
                bh2[0] = Bb[c0*APAD + kc*8 + j];
                bh2[1] = Bb[c0*APAD + kc*8 + j + 4];
                bl2[0] = Bb[GBN*APAD + c0*APAD + kc*8 + j];
                bl2[1] = Bb[GBN*APAD + c0*APAD + kc*8 + j + 4];
                #pragma unroll
                for (int mt = 0; mt < 2; mt++) {
                    mma_bf16(acc[mt][n], ah[mt], bh2);
                    mma_bf16(acc[mt][n], al[mt], bh2);
                    mma_bf16(acc[mt][n], ah[mt], bl2);
                }
            }
        }

        if (t + 1 < nt) {
            int nb = buf ^ 1;
            uint32_t* An = Ash + nb*2*GBM*APAD;
            uint32_t* Bn = Bsh + nb*2*GBN*APAD;
            #pragma unroll
            for (int s = 0; s < 4; s++) {
                float4 v = af[s];
                uint32_t h0 = pack_bf16x2(v.x, v.y);
                uint32_t h1 = pack_bf16x2(v.z, v.w);
                uint32_t l0 = pack_bf16x2(v.x - bf_low(h0), v.y - bf_high(h0));
                uint32_t l1 = pack_bf16x2(v.z - bf_low(h1), v.w - bf_high(h1));
                int row = arow + 32*s;
                uint32_t* ph = An + row*APAD + akp0;
                uint32_t* pl = An + GBM*APAD + row*APAD + akp0;
                ph[0] = h0; ph[1] = h1; pl[0] = l0; pl[1] = l1;
            }
            uint32_t* ph = Bn + bn0*APAD + bkp0;
            uint32_t* pl = Bn + GBN*APAD + bn0*APAD + bkp0;
            ph[0]=bfh.x; ph[1]=bfh.y; ph[2]=bfh.z; ph[3]=bfh.w;
            pl[0]=bfl.x; pl[1]=bfl.y; pl[2]=bfl.z; pl[3]=bfl.w;
        }
        __syncthreads();
    }

    float2 bb[4];
    #pragma unroll
    for (int n = 0; n < 4; n++) {
        if (mode == 2 || mode == 3)
            bb[n] = *(const float2*)(bias + bn + wn + n*8 + 2*j);
        else
            bb[n] = make_float2(0.f, 0.f);
    }
    #pragma unroll
    for (int mt = 0; mt < 2; mt++) {
        int r0 = bm + wm + mt*16 + g;
        #pragma unroll
        for (int n = 0; n < 4; n++) {
            int col = bn + wn + n*8 + 2*j;
            size_t o0 = (size_t)r0*N + col;
            size_t o1 = (size_t)(r0 + 8)*N + col;
            epi2(C, o0, acc[mt][n][0], acc[mt][n][1], bb[n], res, mode);
            epi2(C, o1, acc[mt][n][2], acc[mt][n][3], bb[n], res, mode);
        }
    }
}

// ================= warp-MMA flash attention (split-K, packed Q) =============
#define KT  32
#define NITC (KEYS_PER_CHUNK/KT)   // 16 iterations per chunk

__global__ __launch_bounds__(128, 3)
void attn_mma(const float* __restrict__ gmask) {
    __shared__ __align__(16) uint32_t Ksh[2][2][16][40];
    __shared__ __align__(16) uint32_t Vsh[2][2][32][20];
    __shared__ float sMask[2][KT];   // stores (1-mk)*NEGF

    int tid  = threadIdx.x;
    int warp = tid >> 5;
    int lane = tid & 31;
    int g    = lane >> 2;
    int j    = lane & 3;
    int bh   = blockIdx.y;
    int b    = bh >> 3, h = bh & 7;
    int q0   = blockIdx.x * 128 + warp * 32;
    int z    = blockIdx.z;

    // ---- Q fragments from pre-packed planes (L2E-prescaled) ----
    uint32_t qh[2][2][4], ql[2][2][4];
    float qn2[2][2];
    {
        const uint32_t* qbh = g_qph + ((size_t)bh*SEQ + q0)*16 + j*4;
        const uint32_t* qbl = g_qpl + ((size_t)bh*SEQ + q0)*16 + j*4;
        #pragma unroll
        for (int mt = 0; mt < 2; mt++) {
            #pragma unroll
            for (int rr = 0; rr < 2; rr++) {
                int row = mt*16 + g + rr*8;
                uint4 th  = *(const uint4*)(qbh + (size_t)row*16);
                uint4 tlq = *(const uint4*)(qbl + (size_t)row*16);
                qh[mt][0][rr]   = th.x;  qh[mt][0][rr+2] = th.y;
                qh[mt][1][rr]   = th.z;  qh[mt][1][rr+2] = th.w;
                ql[mt][0][rr]   = tlq.x; ql[mt][0][rr+2] = tlq.y;
                ql[mt][1][rr]   = tlq.z; ql[mt][1][rr+2] = tlq.w;
                qn2[mt][rr] = g_qn[(size_t)bh*SEQ + q0 + row];
            }
        }
    }

    // |q*L2E| * |k| bounds s*log2e; 43.28 = 30*log2e slack
    float kmaxn = sqrtf(__uint_as_float(g_kmax2[bh]));
    float fm[2][2], cb[2][2];
    #pragma unroll
    for (int mt = 0; mt < 2; mt++) {
        fm[mt][0] = gmask[b*SEQ + q0 + mt*16 + g];
        fm[mt][1] = gmask[b*SEQ + q0 + mt*16 + g + 8];
        #pragma unroll
        for (int rr = 0; rr < 2; rr++)
            cb[mt][rr] = (fm[mt][rr] == 0.f) ? 0.f
                       : -(sqrtf(qn2[mt][rr]) * kmaxn - 43.2808512266689f);
    }

    float lrow[2][2], ofr[2][4][4];
    #pragma unroll
    for (int mt = 0; mt < 2; mt++) {
        lrow[mt][0] = 0.f; lrow[mt][1] = 0.f;
        #pragma unroll
        for (int nd = 0; nd < 4; nd++)
            #pragma unroll
            for (int r = 0; r < 4; r++) ofr[mt][nd][r] = 0.f;
    }

    int kdp = tid >> 3;
    int kkg = (tid & 7) * 4;
    int vdm = tid >> 2;
    int vpg = (tid & 3) * 4;
    const uint32_t* kbh = g_kph + ((size_t)bh*16 + kdp)*SEQ + z*KEYS_PER_CHUNK + kkg;
    const uint32_t* kbl = g_kpl + ((size_t)bh*16 + kdp)*SEQ + z*KEYS_PER_CHUNK + kkg;
    const uint32_t* vbh = g_vph + ((size_t)bh*32 + vdm)*(SEQ/2) + z*(KEYS_PER_CHUNK/2) + vpg;
    const uint32_t* vbl = g_vpl + ((size_t)bh*32 + vdm)*(SEQ/2) + z*(KEYS_PER_CHUNK/2) + vpg;
    const float* mbase = gmask + b*SEQ + z*KEYS_PER_CHUNK + tid;

    uint4 rkh, rkl, rvh, rvl; float ml = 0.f;
    rkh = *(const uint4*)(kbh);
    rkl = *(const uint4*)(kbl);
    rvh = *(const uint4*)(vbh);
    rvl = *(const uint4*)(vbl);
    if (tid < KT) ml = *mbase;

    *(uint4*)&Ksh[0][0][kdp][kkg] = rkh;
    *(uint4*)&Ksh[0][1][kdp][kkg] = rkl;
    *(uint4*)&Vsh[0][0][vdm][vpg] = rvh;
    *(uint4*)&Vsh[0][1][vdm][vpg] = rvl;
    if (tid < KT) sMask[0][tid] = (1.0f - ml) * NEGF;
    __syncthreads();

    for (int it = 0; it < NITC; it++) {
        int bufc = it & 1;
        if (it + 1 < NITC) {
            rkh = *(const uint4*)(kbh + (it+1)*KT);
            rkl = *(const uint4*)(kbl + (it+1)*KT);
            rvh = *(const uint4*)(vbh + (it+1)*(KT/2));
            rvl = *(const uint4*)(vbl + (it+1)*(KT/2));
            if (tid < KT) ml = mbase[(it+1)*KT];
        }

        float sfr[2][4][4];
        #pragma unroll
        for (int mt = 0; mt < 2; mt++)
            #pragma unroll
            for (int n = 0; n < 4; n++)
                #pragma unroll
                for (int r = 0; r < 4; r++) sfr[mt][n][r] = 0.f;

        #pragma unroll
        for (int n = 0; n < 4; n++) {
            #pragma unroll
            for (int ks = 0; ks < 2; ks++) {
                uint32_t bhi[2], blo[2];
                bhi[0] = Ksh[bufc][0][ks*8 + j][n*8 + g];
                bhi[1] = Ksh[bufc][0][ks*8 + j + 4][n*8 + g];
                blo[0] = Ksh[bufc][1][ks*8 + j][n*8 + g];
                blo[1] = Ksh[bufc][1][ks*8 + j + 4][n*8 + g];
                #pragma unroll
                for (int mt = 0; mt < 2; mt++) {
                    mma_bf16(sfr[mt][n], qh[mt][ks], bhi);
                    mma_bf16(sfr[mt][n], ql[mt][ks], bhi);
                    mma_bf16(sfr[mt][n], qh[mt][ks], blo);
                }
            }
        }

        // ---- softmax, exp2 domain: p = ex2(fm*(s2 + mk) + cb) ----
        uint32_t phr0[2][4], phr1[2][4], plr0[2][4], plr1[2][4];
        #pragma unroll
        for (int mt = 0; mt < 2; mt++) {
            float f0 = fm[mt][0], f1 = fm[mt][1];
            float c0 = cb[mt][0], c1 = cb[mt][1];
            float ls0 = 0.f, ls1 = 0.f;
            #pragma unroll
            for (int n = 0; n < 4; n++) {
                float mk0 = sMask[bufc][n*8 + 2*j];
                float mk1 = sMask[bufc][n*8 + 2*j + 1];
                float p0 = ex2f(fmaf(f0, sfr[mt][n][0] + mk0, c0));
                float p1 = ex2f(fmaf(f0, sfr[mt][n][1] + mk1, c0));
                float p2 = ex2f(fmaf(f1, sfr[mt][n][2] + mk0, c1));
                float p3 = ex2f(fmaf(f1, sfr[mt][n][3] + mk1, c1));
                ls0 += p0 + p1; ls1 += p2 + p3;
                uint32_t h01 = pack_bf16x2(p0, p1);
                uint32_t h23 = pack_bf16x2(p2, p3);
                phr0[mt][n] = h01;
                phr1[mt][n] = h23;
                plr0[mt][n] = pack_bf16x2(p0 - bf_low(h01), p1 - bf_high(h01));
                plr1[mt][n] = pack_bf16x2(p2 - bf_low(h23), p3 - bf_high(h23));
            }
            lrow[mt][0] += ls0; lrow[mt][1] += ls1;
        }

        #pragma unroll
        for (int nd = 0; nd < 4; nd++) {
            #pragma unroll
            for (int k2 = 0; k2 < 2; k2++) {
                uint32_t bhi[2], blo[2];
                bhi[0] = Vsh[bufc][0][nd*8 + g][k2*8 + j];
                bhi[1] = Vsh[bufc][0][nd*8 + g][k2*8 + j + 4];
                blo[0] = Vsh[bufc][1][nd*8 + g][k2*8 + j];
                blo[1] = Vsh[bufc][1][nd*8 + g][k2*8 + j + 4];
                #pragma unroll
                for (int mt = 0; mt < 2; mt++) {
                    uint32_t ahi[4] = {phr0[mt][2*k2], phr1[mt][2*k2],
                                       phr0[mt][2*k2+1], phr1[mt][2*k2+1]};
                    uint32_t alo[4] = {plr0[mt][2*k2], plr1[mt][2*k2],
                                       plr0[mt][2*k2+1], plr1[mt][2*k2+1]};
                    mma_bf16(ofr[mt][nd], ahi, bhi);
                    mma_bf16(ofr[mt][nd], ahi, blo);
                    mma_bf16(ofr[mt][nd], alo, bhi);
                }
            }
        }

        if (it + 1 < NITC) {
            int bufn = bufc ^ 1;
            *(uint4*)&Ksh[bufn][0][kdp][kkg] = rkh;
            *(uint4*)&Ksh[bufn][1][kdp][kkg] = rkl;
            *(uint4*)&Vsh[bufn][0][vdm][vpg] = rvh;
            *(uint4*)&Vsh[bufn][1][vdm][vpg] = rvl;
            if (tid < KT) sMask[bufn][tid] = (1.0f - ml) * NEGF;
        }
        __syncthreads();
    }

    // ---- epilogue: write RAW partial sums to plane z (exact-once writes) ----
    float* opart = g_opart + (size_t)z * MR * DM;
    #pragma unroll
    for (int mt = 0; mt < 2; mt++) {
        float l0 = lrow[mt][0], l1 = lrow[mt][1];
        l0 += __shfl_xor_sync(0xffffffffu, l0, 1);
        l0 += __shfl_xor_sync(0xffffffffu, l0, 2);
        l1 += __shfl_xor_sync(0xffffffffu, l1, 1);
        l1 += __shfl_xor_sync(0xffffffffu, l1, 2);
        int r0 = q0 + mt*16 + g;
        if (j == 0) {
            g_lpart[((size_t)z*MR + b*SEQ + r0)*NH + h]     = l0;
            g_lpart[((size_t)z*MR + b*SEQ + r0 + 8)*NH + h] = l1;
        }
        #pragma unroll
        for (int nd = 0; nd < 4; nd++) {
            int col = h*DH + nd*8 + 2*j;
            float2 v0 = make_float2(ofr[mt][nd][0], ofr[mt][nd][1]);
            float2 v1 = make_float2(ofr[mt][nd][2], ofr[mt][nd][3]);
            *(float2*)(opart + ((size_t)b*SEQ + r0)*DM + col)     = v0;
            *(float2*)(opart + ((size_t)b*SEQ + r0 + 8)*DM + col) = v1;
        }
    }
}

// ================= combine split-K partials: o = (sum_z O_z) / (sum_z l_z) ==
__global__ void combine_o(float* __restrict__ go) {
    size_t base = ((size_t)blockIdx.x * 256 + threadIdx.x) * 4;
    if (base >= (size_t)MR * DM) return;
    size_t brow = base / DM;
    int col = (int)(base % DM);
    int h = col >> 5;
    float l = 0.f;
    #pragma unroll
    for (int z = 0; z < KSPLIT; z++)
        l += g_lpart[((size_t)z*MR + brow)*NH + h];
    float4 o = make_float4(0.f, 0.f, 0.f, 0.f);
    #pragma unroll
    for (int z = 0; z < KSPLIT; z++) {
        float4 t = *(const float4*)&g_opart[(size_t)z*MR*DM + base];
        o.x += t.x; o.y += t.y; o.z += t.z; o.w += t.w;
    }
    float inv = 1.0f / l;
    o.x *= inv; o.y *= inv; o.z *= inv; o.w *= inv;
    *(float4*)&go[base] = o;
}

// ================= launch =================
extern "C" void kernel_launch(void* const* d_in, const int* in_sizes, int n_in,
                              void* d_out, int out_size) {
    const float* x    = (const float*)d_in[0];
    const float* mask = (const float*)d_in[1];
    const float* Wq   = (const float*)d_in[2];
    const float* Wk   = (const float*)d_in[3];
    const float* Wv   = (const float*)d_in[4];
    const float* Wo   = (const float*)d_in[5];
    const float* W1   = (const float*)d_in[6];
    const float* b1   = (const float*)d_in[7];
    const float* W2   = (const float*)d_in[8];
    const float* b2   = (const float*)d_in[9];
    float* out = (float*)d_out;

    float *qkv_p, *o_p, *xc_p, *ff_p;
    uint32_t *pqkh, *pqkl, *pwoh, *pwol, *pw1h, *pw1l, *pw2h, *pw2l;
    cudaGetSymbolAddress((void**)&qkv_p, g_qkv);
    cudaGetSymbolAddress((void**)&o_p,   g_obuf);
    cudaGetSymbolAddress((void**)&xc_p,  g_xc);
    cudaGetSymbolAddress((void**)&ff_p,  g_ff);
    cudaGetSymbolAddress((void**)&pqkh,  g_pwqkv_h);
    cudaGetSymbolAddress((void**)&pqkl,  g_pwqkv_l);
    cudaGetSymbolAddress((void**)&pwoh,  g_pwo_h);
    cudaGetSymbolAddress((void**)&pwol,  g_pwo_l);
    cudaGetSymbolAddress((void**)&pw1h,  g_pw1_h);
    cudaGetSymbolAddress((void**)&pw1l,  g_pw1_l);
    cudaGetSymbolAddress((void**)&pw2h,  g_pw2_h);
    cudaGetSymbolAddress((void**)&pw2l,  g_pw2_l);

    const int SMEM_GEMM = (2*2*GBM*APAD + 2*2*GBN*APAD) * 4;
    cudaFuncSetAttribute(gemm_mma, cudaFuncAttributeMaxDynamicSharedMemorySize, SMEM_GEMM);

    pack_qkv<<<(NL*3*DM*(DM/2) + 255)/256, 256>>>(Wq, Wk, Wv);
    pack_w<<<(NL*DM*(DM/2) + 255)/256, 256>>>(Wo, pwoh, pwol, DM, DM);
    pack_w<<<(NL*DF*(DM/2) + 255)/256, 256>>>(W1, pw1h, pw1l, DM, DF);
    pack_w<<<(NL*DM*(DF/2) + 255)/256, 256>>>(W2, pw2h, pw2l, DF, DM);

    const size_t QKV_STRIDE = (size_t)MR * DM;

    for (int n = 0; n < NL; n++) {
        const float* xin = (n == 0) ? x : xc_p;

        gemm_mma<<<dim3(DM/GBN, MR/GBM, 3), 256, SMEM_GEMM>>>(
            xin, pqkh + (size_t)n*3*DM*(DM/2), pqkl + (size_t)n*3*DM*(DM/2),
            nullptr, nullptr, qkv_p, MR, DM, DM, 0);

        pack_kv<<<dim3(SEQ/32, NB*NH, 3), dim3(32, 8)>>>(
            qkv_p, qkv_p + QKV_STRIDE, qkv_p + 2*QKV_STRIDE);

        attn_mma<<<dim3(SEQ/128, NB*NH, KSPLIT), 128>>>(mask);

        combine_o<<<(MR*DM/4 + 255)/256, 256>>>(o_p);

        gemm_mma<<<dim3(DM/GBN, MR/GBM, 1), 256, SMEM_GEMM>>>(
            o_p, pwoh + (size_t)n*DM*(DM/2), pwol + (size_t)n*DM*(DM/2),
            nullptr, xin, xc_p, MR, DM, DM, 1);

        gemm_mma<<<dim3(DF/GBN, MR/GBM, 1), 256, SMEM_GEMM>>>(
            xc_p, pw1h + (size_t)n*DF*(DM/2), pw1l + (size_t)n*DF*(DM/2),
            b1 + (size_t)n*DF, nullptr, ff_p, MR, DF, DM, 2);

        float* dst = (n == NL - 1) ? out : xc_p;
        gemm_mma<<<dim3(DM/GBN, MR/GBM, 1), 256, SMEM_GEMM>>>(
            ff_p, pw2h + (size_t)n*DM*(DF/2), pw2l + (size_t)n*DM*(DF/2),
            b2 + (size_t)n*DM, xc_p, dst, MR, DM, DF, 3);
    }
}